// round 8
// baseline (speedup 1.0000x reference)
#include <cuda_runtime.h>
#include <cuda_bf16.h>
#include <cstdint>

#define BB 16
#define NN 4096
#define CC 256

using bf16 = __nv_bfloat16;

// ---------------- scratch (device globals; no allocation allowed) ----------
__device__ __align__(16) bf16  g_xhi[(size_t)BB*NN*CC];   // x split, [B][N][C]
__device__ __align__(16) bf16  g_xlo[(size_t)BB*NN*CC];
__device__ __align__(16) bf16  g_xThi[(size_t)BB*CC*NN];  // x^T split, [B][C][N]
__device__ __align__(16) bf16  g_xTlo[(size_t)BB*CC*NN];
__device__ __align__(16) bf16  g_vhi[(size_t)BB*NN*CC];   // v^T split, [B][N][C]
__device__ __align__(16) bf16  g_vlo[(size_t)BB*NN*CC];
__device__ __align__(16) bf16  g_Whi[3*CC*CC];            // Wq, Wv, Wt split
__device__ __align__(16) bf16  g_Wlo[3*CC*CC];
__device__ float g_u[(size_t)BB*NN*CC];     // u = x.Wt^T, [B][N][C] (side stream)
__device__ float g_t[(size_t)BB*NN*CC];     // pre-BN t, [B][N][C]
__device__ float g_Gp[(size_t)4*BB*CC*CC];  // split-K partials of G
__device__ __align__(16) bf16  g_Ghi[(size_t)BB*CC*CC];
__device__ __align__(16) bf16  g_Glo[(size_t)BB*CC*CC];
__device__ __align__(16) bf16  g_E1hi[(size_t)BB*CC*CC];
__device__ __align__(16) bf16  g_E1lo[(size_t)BB*CC*CC];
__device__ float g_att[(size_t)BB*CC*CC];
__device__ __align__(16) bf16  g_atthi[(size_t)BB*CC*CC];
__device__ __align__(16) bf16  g_attlo[(size_t)BB*CC*CC];
__device__ __align__(16) bf16  g_Ashi[(size_t)BB*CC*CC];  // Wt/colsum split
__device__ __align__(16) bf16  g_Aslo[(size_t)BB*CC*CC];
__device__ __align__(16) bf16  g_Mhi[(size_t)BB*CC*CC];   // NEGATED M split [o][c]
__device__ __align__(16) bf16  g_Mlo[(size_t)BB*CC*CC];
__device__ float g_colsum[BB*CC];
__device__ float g_bns[CC];                 // fused BN Σt per channel
__device__ float g_bnq[CC];                 // fused BN Σt² per channel
__device__ float g_scale[CC];
__device__ float g_shift[CC];

// Stage: Ahi(16K) Alo(16K) Bhi(8K) Blo(8K) = 48KB; 2 stages
#define ST_ALO 16384
#define ST_BHI 32768
#define ST_BLO 40960
#define STAGE  49152
#define SDYN   (2*STAGE)

// ---------------- helpers ---------------------------------------------------
__device__ __forceinline__ uint32_t smem_u32(const void* p){
    uint32_t a;
    asm("{ .reg .u64 t; cvta.to.shared.u64 t, %1; cvt.u32.u64 %0, t; }" : "=r"(a) : "l"(p));
    return a;
}
__device__ __forceinline__ uint32_t sw128(uint32_t o){ return o ^ ((o >> 3) & 0x70); }

__device__ __forceinline__ void ldm4(uint32_t* r, uint32_t addr){
    asm volatile("ldmatrix.sync.aligned.m8n8.x4.shared.b16 {%0,%1,%2,%3}, [%4];"
        : "=r"(r[0]), "=r"(r[1]), "=r"(r[2]), "=r"(r[3]) : "r"(addr));
}
__device__ __forceinline__ void mma_bf16(float* c, const uint32_t* a, const uint32_t* b){
    asm volatile("mma.sync.aligned.m16n8k16.row.col.f32.bf16.bf16.f32 "
        "{%0,%1,%2,%3}, {%4,%5,%6,%7}, {%8,%9}, {%0,%1,%2,%3};"
        : "+f"(c[0]), "+f"(c[1]), "+f"(c[2]), "+f"(c[3])
        : "r"(a[0]), "r"(a[1]), "r"(a[2]), "r"(a[3]), "r"(b[0]), "r"(b[1]));
}
__device__ __forceinline__ void cpa16(uint32_t dst, const void* src){
    asm volatile("cp.async.cg.shared.global [%0], [%1], 16;" :: "r"(dst), "l"(src));
}
__device__ __forceinline__ void split_store(bf16* hi, bf16* lo, size_t i, float v){
    bf16 h = __float2bfloat16(v);
    hi[i] = h;
    lo[i] = __float2bfloat16(v - __bfloat162float(h));
}
__device__ __forceinline__ void split_pair(float v0, float v1, uint32_t& hi, uint32_t& lo){
    bf16 h0 = __float2bfloat16(v0), h1 = __float2bfloat16(v1);
    float r0 = v0 - __bfloat162float(h0), r1 = v1 - __bfloat162float(h1);
    __nv_bfloat162 ph; ph.x = h0; ph.y = h1;
    __nv_bfloat162 pl = __floats2bfloat162_rn(r0, r1);
    hi = *(uint32_t*)&ph;
    lo = *(uint32_t*)&pl;
}

// ---------------------------------------------------------------------------
// Split-bf16 128(M)x64(N) GEMM building blocks, cp.async 2-stage, 2 CTAs/SM.
// ---------------------------------------------------------------------------
__device__ __forceinline__ void ld_chunk(char* smem, int stage, int tid,
        const bf16* __restrict__ Ahi, const bf16* __restrict__ Alo,
        const bf16* __restrict__ Bhi, const bf16* __restrict__ Blo,
        int ldA, int ldB, int c0){
    uint32_t sbase = smem_u32(smem) + stage * STAGE;
    #pragma unroll
    for (int i = 0; i < 4; i++){           // A: 128 rows x 8 segs
        int g = tid + i * 256;
        int row = g >> 3, cg = g & 7;
        uint32_t so = sw128((uint32_t)(row * 128 + cg * 16));
        size_t ga = (size_t)row * ldA + c0 + cg * 8;
        cpa16(sbase + so,          Ahi + ga);
        cpa16(sbase + ST_ALO + so, Alo + ga);
    }
    #pragma unroll
    for (int i = 0; i < 2; i++){           // B: 64 rows x 8 segs
        int g = tid + i * 256;
        int row = g >> 3, cg = g & 7;
        uint32_t so = sw128((uint32_t)(row * 128 + cg * 16));
        size_t gb = (size_t)row * ldB + c0 + cg * 8;
        cpa16(sbase + ST_BHI + so, Bhi + gb);
        cpa16(sbase + ST_BLO + so, Blo + gb);
    }
    asm volatile("cp.async.commit_group;" ::: "memory");
}

__device__ __forceinline__ void compute_chunk(uint32_t sb, int lane,
        int warpM, int warpN, float acc[2][4][4]){
    #pragma unroll
    for (int ks = 0; ks < 4; ks++){
        uint32_t ahi[2][4], alo[2][4];
        #pragma unroll
        for (int mf = 0; mf < 2; mf++){
            int row = warpM * 32 + mf * 16 + (lane & 15);
            uint32_t off = sw128((uint32_t)(row * 128 + ks * 32 + (lane >> 4) * 16));
            ldm4(ahi[mf], sb + off);
            ldm4(alo[mf], sb + ST_ALO + off);
        }
        #pragma unroll
        for (int ng = 0; ng < 2; ng++){
            int rowb = warpN * 32 + ng * 16 + (lane & 15);
            uint32_t off = sw128((uint32_t)(rowb * 128 + ks * 32 + (lane >> 4) * 16));
            uint32_t bh[4], bl[4];
            ldm4(bh, sb + ST_BHI + off);
            ldm4(bl, sb + ST_BLO + off);
            uint32_t bh0[2] = {bh[0], bh[2]}, bh1[2] = {bh[1], bh[3]};
            uint32_t bl0[2] = {bl[0], bl[2]}, bl1[2] = {bl[1], bl[3]};
            #pragma unroll
            for (int mf = 0; mf < 2; mf++){
                mma_bf16(acc[mf][ng*2],     ahi[mf], bh0);
                mma_bf16(acc[mf][ng*2],     ahi[mf], bl0);
                mma_bf16(acc[mf][ng*2],     alo[mf], bh0);
                mma_bf16(acc[mf][ng*2 + 1], ahi[mf], bh1);
                mma_bf16(acc[mf][ng*2 + 1], ahi[mf], bl1);
                mma_bf16(acc[mf][ng*2 + 1], alo[mf], bh1);
            }
        }
    }
}

__device__ __forceinline__ void gemm_main(char* smem,
        const bf16* __restrict__ Ahi, const bf16* __restrict__ Alo, int ldA,
        const bf16* __restrict__ Bhi, const bf16* __restrict__ Blo, int ldB,
        int nChunks, float acc[2][4][4])
{
    int tid = threadIdx.x, lane = tid & 31, wid = tid >> 5;
    int warpM = wid & 3, warpN = wid >> 2;
    uint32_t sb0 = smem_u32(smem);

    ld_chunk(smem, 0, tid, Ahi, Alo, Bhi, Blo, ldA, ldB, 0);
    for (int cc = 0; cc < nChunks; cc++){
        if (cc + 1 < nChunks){
            ld_chunk(smem, (cc + 1) & 1, tid, Ahi, Alo, Bhi, Blo, ldA, ldB, (cc + 1) * 64);
            asm volatile("cp.async.wait_group 1;" ::: "memory");
        } else {
            asm volatile("cp.async.wait_group 0;" ::: "memory");
        }
        __syncthreads();
        compute_chunk(sb0 + (cc & 1) * STAGE, lane, warpM, warpN, acc);
        __syncthreads();
    }
}

// ---------------- conversion: x -> split x AND split x^T --------------------
__global__ void __launch_bounds__(256) k_cvt_x(const float* __restrict__ x){
    int b = blockIdx.z, n0 = blockIdx.x * 64, c0 = blockIdx.y * 64;
    __shared__ float xs[64][65];
    int t = threadIdx.x;
    const float* xb = x + ((size_t)b * NN + n0) * CC + c0;
    #pragma unroll
    for (int p = 0; p < 4; p++){
        int row = p * 16 + (t >> 4);
        int c4  = (t & 15) * 4;
        float4 v = *(const float4*)(xb + (size_t)row * CC + c4);
        uint32_t h0, l0, h1, l1;
        split_pair(v.x, v.y, h0, l0);
        split_pair(v.z, v.w, h1, l1);
        size_t di = ((size_t)b * NN + n0 + row) * CC + c0 + c4;
        *(uint2*)(g_xhi + di) = make_uint2(h0, h1);
        *(uint2*)(g_xlo + di) = make_uint2(l0, l1);
        xs[row][c4 + 0] = v.x; xs[row][c4 + 1] = v.y;
        xs[row][c4 + 2] = v.z; xs[row][c4 + 3] = v.w;
    }
    __syncthreads();
    #pragma unroll
    for (int p = 0; p < 4; p++){
        int cl = p * 16 + (t >> 4);
        int n4 = (t & 15) * 4;
        float v0 = xs[n4][cl], v1 = xs[n4+1][cl], v2 = xs[n4+2][cl], v3 = xs[n4+3][cl];
        uint32_t h0, l0, h1, l1;
        split_pair(v0, v1, h0, l0);
        split_pair(v2, v3, h1, l1);
        size_t di = ((size_t)b * CC + c0 + cl) * NN + n0 + n4;
        *(uint2*)(g_xThi + di) = make_uint2(h0, h1);
        *(uint2*)(g_xTlo + di) = make_uint2(l0, l1);
    }
}
__global__ void k_cvt_w(const float* __restrict__ Wq, const float* __restrict__ Wv,
                        const float* __restrict__ Wt){
    int idx = blockIdx.x * blockDim.x + threadIdx.x;
    int which = idx >> 16, rem = idx & 65535;
    const float* s = (which == 0) ? Wq : (which == 1) ? Wv : Wt;
    split_store(g_Whi, g_Wlo, idx, s[rem]);
}

// ---------------- KT1: v^T (side stream) ------------------------------------
__global__ void __launch_bounds__(256, 2)
kt1(const float* __restrict__ bv){
    extern __shared__ char smem[];
    int b = blockIdx.z;
    size_t xoff = (size_t)b * NN * CC;
    int mBase = blockIdx.x * 128, nBase = blockIdx.y * 64;
    const bf16* Ahi = g_xhi + xoff + (size_t)mBase * CC;
    const bf16* Alo = g_xlo + xoff + (size_t)mBase * CC;
    const bf16* Bhi = g_Whi + CC * CC + nBase * CC;
    const bf16* Blo = g_Wlo + CC * CC + nBase * CC;
    float acc[2][4][4] = {};
    gemm_main(smem, Ahi, Alo, CC, Bhi, Blo, CC, 4, acc);

    int tid = threadIdx.x, lane = tid & 31, wid = tid >> 5;
    int warpM = wid & 3, warpN = wid >> 2;
    int gr = lane >> 2, gc = (lane & 3) * 2;
    #pragma unroll
    for (int mf = 0; mf < 2; mf++)
        #pragma unroll
        for (int nf = 0; nf < 4; nf++){
            float* c = acc[mf][nf];
            int row0 = warpM * 32 + mf * 16 + gr;
            int col  = warpN * 32 + nf * 8 + gc;
            #pragma unroll
            for (int h = 0; h < 2; h++){
                int n = mBase + row0 + h * 8, o = nBase + col;
                size_t di = ((size_t)b * NN + n) * CC + o;
                uint32_t hi, lo;
                split_pair(c[2*h] + bv[o], c[2*h+1] + bv[o+1], hi, lo);
                *(uint32_t*)(g_vhi + di) = hi;
                *(uint32_t*)(g_vlo + di) = lo;
            }
        }
}

// ---------------- KTU: u = x.Wt^T fp32 (side stream) ------------------------
__global__ void __launch_bounds__(256, 2)
ktu(){
    extern __shared__ char smem[];
    int b = blockIdx.z;
    size_t xoff = (size_t)b * NN * CC;
    int mBase = blockIdx.x * 128, nBase = blockIdx.y * 64;
    const bf16* Ahi = g_xhi + xoff + (size_t)mBase * CC;
    const bf16* Alo = g_xlo + xoff + (size_t)mBase * CC;
    const bf16* Bhi = g_Whi + 2 * CC * CC + nBase * CC;
    const bf16* Blo = g_Wlo + 2 * CC * CC + nBase * CC;
    float acc[2][4][4] = {};
    gemm_main(smem, Ahi, Alo, CC, Bhi, Blo, CC, 4, acc);

    int tid = threadIdx.x, lane = tid & 31, wid = tid >> 5;
    int warpM = wid & 3, warpN = wid >> 2;
    int gr = lane >> 2, gc = (lane & 3) * 2;
    #pragma unroll
    for (int mf = 0; mf < 2; mf++)
        #pragma unroll
        for (int nf = 0; nf < 4; nf++){
            float* c = acc[mf][nf];
            int row0 = warpM * 32 + mf * 16 + gr;
            int col  = warpN * 32 + nf * 8 + gc;
            #pragma unroll
            for (int h = 0; h < 2; h++){
                int n = mBase + row0 + h * 8, o = nBase + col;
                *(float2*)(g_u + ((size_t)b * NN + n) * CC + o)
                    = make_float2(c[2*h], c[2*h+1]);
            }
        }
}

// ---------------- KTG: G = x^T x (split-K x4, symmetric: 6 of 8 tiles) ------
__constant__ int c_tileC[6] = {0, 0, 0, 0, 128, 128};
__constant__ int c_tileD[6] = {0, 64, 128, 192, 128, 192};
__global__ void __launch_bounds__(256, 2)
ktG(){
    extern __shared__ char smem[];
    int b = blockIdx.z >> 2, ks = blockIdx.z & 3;
    int cBase = c_tileC[blockIdx.x], dBase = c_tileD[blockIdx.x];
    size_t kOff = (size_t)ks * 1024;
    const bf16* Ah = g_xThi + ((size_t)b * CC + cBase) * NN + kOff;
    const bf16* Al = g_xTlo + ((size_t)b * CC + cBase) * NN + kOff;
    const bf16* Bh = g_xThi + ((size_t)b * CC + dBase) * NN + kOff;
    const bf16* Bl = g_xTlo + ((size_t)b * CC + dBase) * NN + kOff;
    float acc[2][4][4] = {};
    gemm_main(smem, Ah, Al, NN, Bh, Bl, NN, 16, acc);

    int tid = threadIdx.x, lane = tid & 31, wid = tid >> 5;
    int warpM = wid & 3, warpN = wid >> 2;
    int gr = lane >> 2, gc = (lane & 3) * 2;
    float* dst = g_Gp + ((size_t)(ks * BB + b)) * CC * CC;
    #pragma unroll
    for (int mf = 0; mf < 2; mf++)
        #pragma unroll
        for (int nf = 0; nf < 4; nf++){
            float* c = acc[mf][nf];
            int row0 = warpM * 32 + mf * 16 + gr;
            int col  = warpN * 32 + nf * 8 + gc;
            #pragma unroll
            for (int h = 0; h < 2; h++)
                *(float2*)(dst + (size_t)(cBase + row0 + h*8) * CC + dBase + col)
                    = make_float2(c[2*h], c[2*h+1]);
        }
}
// sum split-K partials; mirror the uncomputed lower-left quadrant (r>=128,c<128)
__global__ void k_gsum(){
    size_t i = ((size_t)blockIdx.x * blockDim.x + threadIdx.x) * 4;
    const size_t S = (size_t)BB * CC * CC;
    int b  = (int)(i >> 16);
    int rc = (int)(i & 65535);
    int r = rc >> 8, c0 = rc & 255;
    float v[4];
    if (r >= 128 && c0 < 128){
        #pragma unroll
        for (int j = 0; j < 4; j++){
            size_t src = (size_t)b * CC * CC + (size_t)(c0 + j) * CC + r;  // transposed
            v[j] = g_Gp[src] + g_Gp[S + src] + g_Gp[2*S + src] + g_Gp[3*S + src];
        }
    } else {
        float4 a = *(const float4*)(g_Gp + i);
        float4 bb = *(const float4*)(g_Gp + S + i);
        float4 cc = *(const float4*)(g_Gp + 2*S + i);
        float4 d = *(const float4*)(g_Gp + 3*S + i);
        v[0] = a.x+bb.x+cc.x+d.x; v[1] = a.y+bb.y+cc.y+d.y;
        v[2] = a.z+bb.z+cc.z+d.z; v[3] = a.w+bb.w+cc.w+d.w;
    }
    uint32_t h0,l0,h1,l1;
    split_pair(v[0],v[1],h0,l0); split_pair(v[2],v[3],h1,l1);
    *(uint2*)(g_Ghi + i) = make_uint2(h0,h1);
    *(uint2*)(g_Glo + i) = make_uint2(l0,l1);
}

// ---------------- small square GEMMs (K=256) --------------------------------
// mode 0: E1 = Wq.G ; mode 1: E = E1.Wq^T (fp32) ; mode 2: -M = -(As.att) split
__global__ void __launch_bounds__(256, 2)
ksq(int mode){
    extern __shared__ char smem[];
    int b = blockIdx.z;
    int mBase = blockIdx.y * 128, nBase = blockIdx.x * 64;
    size_t boff = (size_t)b * CC * CC;
    const bf16 *Ah, *Al, *Bh, *Bl;
    if (mode == 0){
        Ah = g_Whi + mBase * CC;        Al = g_Wlo + mBase * CC;
        Bh = g_Ghi + boff + nBase * CC; Bl = g_Glo + boff + nBase * CC;
    } else if (mode == 1){
        Ah = g_E1hi + boff + mBase * CC; Al = g_E1lo + boff + mBase * CC;
        Bh = g_Whi + nBase * CC;         Bl = g_Wlo + nBase * CC;
    } else {
        Ah = g_Ashi + boff + mBase * CC;  Al = g_Aslo + boff + mBase * CC;
        Bh = g_atthi + boff + nBase * CC; Bl = g_attlo + boff + nBase * CC;
    }
    float acc[2][4][4] = {};
    gemm_main(smem, Ah, Al, CC, Bh, Bl, CC, 4, acc);

    int tid = threadIdx.x, lane = tid & 31, wid = tid >> 5;
    int warpM = wid & 3, warpN = wid >> 2;
    int gr = lane >> 2, gc = (lane & 3) * 2;
    #pragma unroll
    for (int mf = 0; mf < 2; mf++)
        #pragma unroll
        for (int nf = 0; nf < 4; nf++){
            float* c = acc[mf][nf];
            int row0 = warpM * 32 + mf * 16 + gr;
            int col  = warpN * 32 + nf * 8 + gc;
            #pragma unroll
            for (int h = 0; h < 2; h++){
                size_t di = boff + (size_t)(mBase + row0 + h*8) * CC + nBase + col;
                if (mode == 1){
                    *(float2*)(g_att + di) = make_float2(c[2*h], c[2*h+1]);
                } else if (mode == 0){
                    uint32_t hi, lo;
                    split_pair(c[2*h], c[2*h+1], hi, lo);
                    *(uint32_t*)(g_E1hi + di) = hi; *(uint32_t*)(g_E1lo + di) = lo;
                } else {
                    uint32_t hi, lo;
                    split_pair(-c[2*h], -c[2*h+1], hi, lo);   // store NEGATED M
                    *(uint32_t*)(g_Mhi + di) = hi; *(uint32_t*)(g_Mlo + di) = lo;
                }
            }
        }
}

// ---------------- softmax / colsum / As ------------------------------------
__global__ void k_softmax(){
    size_t row = blockIdx.x;
    float* p = g_att + row * CC;
    int t = threadIdx.x;
    float v = p[t];
    __shared__ float red[256];
    red[t] = v; __syncthreads();
    for (int s = 128; s > 0; s >>= 1){ if (t < s) red[t] = fmaxf(red[t], red[t+s]); __syncthreads(); }
    float mx = red[0]; __syncthreads();
    float e = __expf(v - mx);
    red[t] = e; __syncthreads();
    for (int s = 128; s > 0; s >>= 1){ if (t < s) red[t] += red[t+s]; __syncthreads(); }
    float val = e / red[0];
    p[t] = val;
    split_store(g_atthi, g_attlo, row * CC + t, val);
}
__global__ void k_colsum(){
    int b = blockIdx.x, d = threadIdx.x;
    float s = 0.f;
    for (int c = 0; c < CC; c++) s += g_att[((size_t)b * CC + c) * CC + d];
    g_colsum[b * CC + d] = s;
}
__global__ void k_scaleWt(const float* __restrict__ Wt){
    // side duty: zero the fused-BN accumulators (always precedes kt6)
    if (blockIdx.x == 0){ g_bns[threadIdx.x] = 0.f; g_bnq[threadIdx.x] = 0.f; }
    size_t i = ((size_t)blockIdx.x * blockDim.x + threadIdx.x) * 4;
    int b = (int)(i >> 16);
    int od = (int)(i & 65535);
    int d = od & 255;
    float4 w = *(const float4*)(Wt + od);
    float4 cs = *(const float4*)(g_colsum + b * CC + d);
    float v0 = w.x / (1e-9f + cs.x), v1 = w.y / (1e-9f + cs.y);
    float v2 = w.z / (1e-9f + cs.z), v3 = w.w / (1e-9f + cs.w);
    uint32_t h0,l0,h1,l1;
    split_pair(v0,v1,h0,l0); split_pair(v2,v3,h1,l1);
    *(uint2*)(g_Ashi + i) = make_uint2(h0,h1);
    *(uint2*)(g_Aslo + i) = make_uint2(l0,l1);
}

// ---------------- KT6: t = u + v.(-M)^T + bt  (K=256) + fused BN sums -------
__global__ void __launch_bounds__(256, 2)
kt6(const float* __restrict__ bt){
    extern __shared__ char smem[];
    int b = blockIdx.z;
    int mBase = blockIdx.x * 128;   // n
    int oBase = blockIdx.y * 64;    // o
    size_t nrow = (size_t)b * NN + mBase;
    size_t boff = (size_t)b * CC * CC;
    const bf16* Ah = g_vhi + nrow * CC;
    const bf16* Al = g_vlo + nrow * CC;
    const bf16* Bh = g_Mhi + boff + oBase * CC;
    const bf16* Bl = g_Mlo + boff + oBase * CC;

    float acc[2][4][4] = {};
    gemm_main(smem, Ah, Al, CC, Bh, Bl, CC, 4, acc);

    int tid = threadIdx.x, lane = tid & 31, wid = tid >> 5;
    int warpM = wid & 3, warpN = wid >> 2;

    __shared__ float bn_s[64], bn_q[64];
    if (tid < 64){ bn_s[tid] = 0.f; bn_q[tid] = 0.f; }
    __syncthreads();

    int gr = lane >> 2, gc = (lane & 3) * 2;
    float sA[4][2], qA[4][2];
    #pragma unroll
    for (int nf = 0; nf < 4; nf++){
        sA[nf][0] = sA[nf][1] = qA[nf][0] = qA[nf][1] = 0.f;
        int col = warpN * 32 + nf * 8 + gc;
        int o = oBase + col;
        float b0 = bt[o], b1 = bt[o + 1];
        #pragma unroll
        for (int mf = 0; mf < 2; mf++){
            float* c = acc[mf][nf];
            int row0 = warpM * 32 + mf * 16 + gr;
            #pragma unroll
            for (int h = 0; h < 2; h++){
                int n = mBase + row0 + h * 8;
                size_t di = ((size_t)b * NN + n) * CC + o;
                float2 u2 = *(const float2*)(g_u + di);
                float v0 = c[2*h]   + u2.x + b0;
                float v1 = c[2*h+1] + u2.y + b1;
                *(float2*)(g_t + di) = make_float2(v0, v1);
                sA[nf][0] += v0;       sA[nf][1] += v1;
                qA[nf][0] += v0 * v0;  qA[nf][1] += v1 * v1;
            }
        }
    }
    #pragma unroll
    for (int nf = 0; nf < 4; nf++){
        #pragma unroll
        for (int st = 4; st < 32; st <<= 1){
            sA[nf][0] += __shfl_down_sync(0xffffffffu, sA[nf][0], st);
            sA[nf][1] += __shfl_down_sync(0xffffffffu, sA[nf][1], st);
            qA[nf][0] += __shfl_down_sync(0xffffffffu, qA[nf][0], st);
            qA[nf][1] += __shfl_down_sync(0xffffffffu, qA[nf][1], st);
        }
    }
    if (lane < 4){
        #pragma unroll
        for (int nf = 0; nf < 4; nf++){
            int colL = warpN * 32 + nf * 8 + lane * 2;
            atomicAdd(&bn_s[colL],     sA[nf][0]);
            atomicAdd(&bn_s[colL + 1], sA[nf][1]);
            atomicAdd(&bn_q[colL],     qA[nf][0]);
            atomicAdd(&bn_q[colL + 1], qA[nf][1]);
        }
    }
    __syncthreads();
    if (tid < 64){
        atomicAdd(&g_bns[oBase + tid], bn_s[tid]);
        atomicAdd(&g_bnq[oBase + tid], bn_q[tid]);
    }
}

// ---------------- BN finalize + final --------------------------------------
__global__ void k_bnfin(const float* __restrict__ gamma, const float* __restrict__ beta){
    int o = threadIdx.x;
    float inv = 1.0f / (float)(BB * NN);
    float mean = g_bns[o] * inv;
    float var  = g_bnq[o] * inv - mean * mean;
    float rstd = rsqrtf(var + 1e-5f);
    float sc = gamma[o] * rstd;
    g_scale[o] = sc;
    g_shift[o] = beta[o] - mean * sc;
}
__global__ void k_final(const float* __restrict__ x, float* __restrict__ out){
    size_t i = ((size_t)blockIdx.x * blockDim.x + threadIdx.x) * 4;
    int o = (int)(i & (CC - 1));
    float4 t4 = *(const float4*)(g_t + i);
    float4 x4 = *(const float4*)(x + i);
    float4 sc = *(const float4*)(g_scale + o);
    float4 sh = *(const float4*)(g_shift + o);
    float4 r;
    r.x = x4.x + fmaxf(fmaf(t4.x, sc.x, sh.x), 0.f);
    r.y = x4.y + fmaxf(fmaf(t4.y, sc.y, sh.y), 0.f);
    r.z = x4.z + fmaxf(fmaf(t4.z, sc.z, sh.z), 0.f);
    r.w = x4.w + fmaxf(fmaf(t4.w, sc.w, sh.w), 0.f);
    *(float4*)(out + i) = r;
}

// ---------------- launch ----------------------------------------------------
extern "C" void kernel_launch(void* const* d_in, const int* in_sizes, int n_in,
                              void* d_out, int out_size){
    (void)in_sizes; (void)n_in; (void)out_size;
    const float* x     = (const float*)d_in[1];
    const float* Wq    = (const float*)d_in[2];
    const float* Wv    = (const float*)d_in[3];
    const float* bv    = (const float*)d_in[4];
    const float* Wt    = (const float*)d_in[5];
    const float* bt    = (const float*)d_in[6];
    const float* gamma = (const float*)d_in[7];
    const float* beta  = (const float*)d_in[8];
    float* out = (float*)d_out;

    static cudaStream_t s2 = nullptr;
    static cudaEvent_t eFork = nullptr, eJoin = nullptr;
    if (!s2){
        cudaStreamCreateWithFlags(&s2, cudaStreamNonBlocking);
        cudaEventCreateWithFlags(&eFork, cudaEventDisableTiming);
        cudaEventCreateWithFlags(&eJoin, cudaEventDisableTiming);
        cudaFuncSetAttribute(kt1, cudaFuncAttributeMaxDynamicSharedMemorySize, SDYN);
        cudaFuncSetAttribute(ktu, cudaFuncAttributeMaxDynamicSharedMemorySize, SDYN);
        cudaFuncSetAttribute(ktG, cudaFuncAttributeMaxDynamicSharedMemorySize, SDYN);
        cudaFuncSetAttribute(ksq, cudaFuncAttributeMaxDynamicSharedMemorySize, SDYN);
        cudaFuncSetAttribute(kt6, cudaFuncAttributeMaxDynamicSharedMemorySize, SDYN);
    }

    k_cvt_x  <<<dim3(64, 4, BB), 256>>>(x);
    k_cvt_w  <<<768, 256>>>(Wq, Wv, Wt);

    // fork: v-projection + u-projection run concurrently with attention chain
    cudaEventRecord(eFork, 0);
    cudaStreamWaitEvent(s2, eFork, 0);
    kt1      <<<dim3(32, 4, BB), 256, SDYN, s2>>>(bv);
    ktu      <<<dim3(32, 4, BB), 256, SDYN, s2>>>();
    cudaEventRecord(eJoin, s2);

    ktG      <<<dim3(6, 1, 4*BB), 256, SDYN>>>();
    k_gsum   <<<1024, 256>>>();
    ksq      <<<dim3(4, 2, BB), 256, SDYN>>>(0);
    ksq      <<<dim3(4, 2, BB), 256, SDYN>>>(1);
    k_softmax<<<BB*CC, 256>>>();
    k_colsum <<<BB, 256>>>();
    k_scaleWt<<<1024, 256>>>(Wt);
    ksq      <<<dim3(4, 2, BB), 256, SDYN>>>(2);

    cudaStreamWaitEvent(0, eJoin, 0);     // join before kt6
    kt6      <<<dim3(32, 4, BB), 256, SDYN>>>(bt);
    k_bnfin  <<<1, 256>>>(gamma, beta);
    k_final  <<<16384, 256>>>(x, out);
}

// round 9
// speedup vs baseline: 1.0364x; 1.0364x over previous
#include <cuda_runtime.h>
#include <cuda_bf16.h>
#include <cstdint>

#define BB 16
#define NN 4096
#define CC 256

using bf16 = __nv_bfloat16;

// ---------------- scratch (device globals; no allocation allowed) ----------
__device__ __align__(16) bf16  g_xhi[(size_t)BB*NN*CC];   // x split, [B][N][C]
__device__ __align__(16) bf16  g_xlo[(size_t)BB*NN*CC];
__device__ __align__(16) bf16  g_xThi[(size_t)BB*CC*NN];  // x^T split, [B][C][N]
__device__ __align__(16) bf16  g_xTlo[(size_t)BB*CC*NN];
__device__ __align__(16) bf16  g_vhi[(size_t)BB*NN*CC];   // v^T split, [B][N][C]
__device__ __align__(16) bf16  g_vlo[(size_t)BB*NN*CC];
__device__ __align__(16) bf16  g_Whi[3*CC*CC];            // Wq, Wv, Wt split
__device__ __align__(16) bf16  g_Wlo[3*CC*CC];
__device__ float g_t[(size_t)BB*NN*CC];     // pre-BN t, [B][N][C]
__device__ float g_Gp[(size_t)3*BB*CC*CC];  // split-K partials of G (3 ways)
__device__ __align__(16) bf16  g_Ghi[(size_t)BB*CC*CC];
__device__ __align__(16) bf16  g_Glo[(size_t)BB*CC*CC];
__device__ __align__(16) bf16  g_E1hi[(size_t)BB*CC*CC];
__device__ __align__(16) bf16  g_E1lo[(size_t)BB*CC*CC];
__device__ float g_att[(size_t)BB*CC*CC];
__device__ __align__(16) bf16  g_atthi[(size_t)BB*CC*CC]; // att/colsum split
__device__ __align__(16) bf16  g_attlo[(size_t)BB*CC*CC];
__device__ __align__(16) bf16  g_Mhi[(size_t)BB*CC*CC];   // NEGATED M split [o][c]
__device__ __align__(16) bf16  g_Mlo[(size_t)BB*CC*CC];
__device__ float g_colsum[BB*CC];
__device__ float g_bns[CC];                 // fused BN Σt per channel
__device__ float g_bnq[CC];                 // fused BN Σt² per channel
__device__ float g_scale[CC];
__device__ float g_shift[CC];

// Stage: Ahi(16K) Alo(16K) Bhi(8K) Blo(8K) = 48KB; 2 stages
#define ST_ALO 16384
#define ST_BHI 32768
#define ST_BLO 40960
#define STAGE  49152
#define SDYN   (2*STAGE)

// ---------------- helpers ---------------------------------------------------
__device__ __forceinline__ uint32_t smem_u32(const void* p){
    uint32_t a;
    asm("{ .reg .u64 t; cvta.to.shared.u64 t, %1; cvt.u32.u64 %0, t; }" : "=r"(a) : "l"(p));
    return a;
}
__device__ __forceinline__ uint32_t sw128(uint32_t o){ return o ^ ((o >> 3) & 0x70); }

__device__ __forceinline__ void ldm4(uint32_t* r, uint32_t addr){
    asm volatile("ldmatrix.sync.aligned.m8n8.x4.shared.b16 {%0,%1,%2,%3}, [%4];"
        : "=r"(r[0]), "=r"(r[1]), "=r"(r[2]), "=r"(r[3]) : "r"(addr));
}
__device__ __forceinline__ void mma_bf16(float* c, const uint32_t* a, const uint32_t* b){
    asm volatile("mma.sync.aligned.m16n8k16.row.col.f32.bf16.bf16.f32 "
        "{%0,%1,%2,%3}, {%4,%5,%6,%7}, {%8,%9}, {%0,%1,%2,%3};"
        : "+f"(c[0]), "+f"(c[1]), "+f"(c[2]), "+f"(c[3])
        : "r"(a[0]), "r"(a[1]), "r"(a[2]), "r"(a[3]), "r"(b[0]), "r"(b[1]));
}
__device__ __forceinline__ void cpa16(uint32_t dst, const void* src){
    asm volatile("cp.async.cg.shared.global [%0], [%1], 16;" :: "r"(dst), "l"(src));
}
__device__ __forceinline__ void split_store(bf16* hi, bf16* lo, size_t i, float v){
    bf16 h = __float2bfloat16(v);
    hi[i] = h;
    lo[i] = __float2bfloat16(v - __bfloat162float(h));
}
__device__ __forceinline__ void split_pair(float v0, float v1, uint32_t& hi, uint32_t& lo){
    bf16 h0 = __float2bfloat16(v0), h1 = __float2bfloat16(v1);
    float r0 = v0 - __bfloat162float(h0), r1 = v1 - __bfloat162float(h1);
    __nv_bfloat162 ph; ph.x = h0; ph.y = h1;
    __nv_bfloat162 pl = __floats2bfloat162_rn(r0, r1);
    hi = *(uint32_t*)&ph;
    lo = *(uint32_t*)&pl;
}

// ---------------------------------------------------------------------------
// Split-bf16 128(M)x64(N) GEMM building blocks, cp.async 2-stage, 2 CTAs/SM.
// ---------------------------------------------------------------------------
__device__ __forceinline__ void ld_chunk(char* smem, int stage, int tid,
        const bf16* __restrict__ Ahi, const bf16* __restrict__ Alo,
        const bf16* __restrict__ Bhi, const bf16* __restrict__ Blo,
        int ldA, int ldB, int c0){
    uint32_t sbase = smem_u32(smem) + stage * STAGE;
    #pragma unroll
    for (int i = 0; i < 4; i++){           // A: 128 rows x 8 segs
        int g = tid + i * 256;
        int row = g >> 3, cg = g & 7;
        uint32_t so = sw128((uint32_t)(row * 128 + cg * 16));
        size_t ga = (size_t)row * ldA + c0 + cg * 8;
        cpa16(sbase + so,          Ahi + ga);
        cpa16(sbase + ST_ALO + so, Alo + ga);
    }
    #pragma unroll
    for (int i = 0; i < 2; i++){           // B: 64 rows x 8 segs
        int g = tid + i * 256;
        int row = g >> 3, cg = g & 7;
        uint32_t so = sw128((uint32_t)(row * 128 + cg * 16));
        size_t gb = (size_t)row * ldB + c0 + cg * 8;
        cpa16(sbase + ST_BHI + so, Bhi + gb);
        cpa16(sbase + ST_BLO + so, Blo + gb);
    }
    asm volatile("cp.async.commit_group;" ::: "memory");
}

__device__ __forceinline__ void compute_chunk(uint32_t sb, int lane,
        int warpM, int warpN, float acc[2][4][4]){
    #pragma unroll
    for (int ks = 0; ks < 4; ks++){
        uint32_t ahi[2][4], alo[2][4];
        #pragma unroll
        for (int mf = 0; mf < 2; mf++){
            int row = warpM * 32 + mf * 16 + (lane & 15);
            uint32_t off = sw128((uint32_t)(row * 128 + ks * 32 + (lane >> 4) * 16));
            ldm4(ahi[mf], sb + off);
            ldm4(alo[mf], sb + ST_ALO + off);
        }
        #pragma unroll
        for (int ng = 0; ng < 2; ng++){
            int rowb = warpN * 32 + ng * 16 + (lane & 15);
            uint32_t off = sw128((uint32_t)(rowb * 128 + ks * 32 + (lane >> 4) * 16));
            uint32_t bh[4], bl[4];
            ldm4(bh, sb + ST_BHI + off);
            ldm4(bl, sb + ST_BLO + off);
            uint32_t bh0[2] = {bh[0], bh[2]}, bh1[2] = {bh[1], bh[3]};
            uint32_t bl0[2] = {bl[0], bl[2]}, bl1[2] = {bl[1], bl[3]};
            #pragma unroll
            for (int mf = 0; mf < 2; mf++){
                mma_bf16(acc[mf][ng*2],     ahi[mf], bh0);
                mma_bf16(acc[mf][ng*2],     ahi[mf], bl0);
                mma_bf16(acc[mf][ng*2],     alo[mf], bh0);
                mma_bf16(acc[mf][ng*2 + 1], ahi[mf], bh1);
                mma_bf16(acc[mf][ng*2 + 1], ahi[mf], bl1);
                mma_bf16(acc[mf][ng*2 + 1], alo[mf], bh1);
            }
        }
    }
}

__device__ __forceinline__ void gemm_main(char* smem,
        const bf16* __restrict__ Ahi, const bf16* __restrict__ Alo, int ldA,
        const bf16* __restrict__ Bhi, const bf16* __restrict__ Blo, int ldB,
        int nChunks, float acc[2][4][4])
{
    int tid = threadIdx.x, lane = tid & 31, wid = tid >> 5;
    int warpM = wid & 3, warpN = wid >> 2;
    uint32_t sb0 = smem_u32(smem);

    ld_chunk(smem, 0, tid, Ahi, Alo, Bhi, Blo, ldA, ldB, 0);
    for (int cc = 0; cc < nChunks; cc++){
        if (cc + 1 < nChunks){
            ld_chunk(smem, (cc + 1) & 1, tid, Ahi, Alo, Bhi, Blo, ldA, ldB, (cc + 1) * 64);
            asm volatile("cp.async.wait_group 1;" ::: "memory");
        } else {
            asm volatile("cp.async.wait_group 0;" ::: "memory");
        }
        __syncthreads();
        compute_chunk(sb0 + (cc & 1) * STAGE, lane, warpM, warpN, acc);
        __syncthreads();
    }
}

// ---------------- conversion: x -> split x AND split x^T --------------------
__global__ void __launch_bounds__(256) k_cvt_x(const float* __restrict__ x){
    int b = blockIdx.z, n0 = blockIdx.x * 64, c0 = blockIdx.y * 64;
    __shared__ float xs[64][65];
    int t = threadIdx.x;
    const float* xb = x + ((size_t)b * NN + n0) * CC + c0;
    #pragma unroll
    for (int p = 0; p < 4; p++){
        int row = p * 16 + (t >> 4);
        int c4  = (t & 15) * 4;
        float4 v = *(const float4*)(xb + (size_t)row * CC + c4);
        uint32_t h0, l0, h1, l1;
        split_pair(v.x, v.y, h0, l0);
        split_pair(v.z, v.w, h1, l1);
        size_t di = ((size_t)b * NN + n0 + row) * CC + c0 + c4;
        *(uint2*)(g_xhi + di) = make_uint2(h0, h1);
        *(uint2*)(g_xlo + di) = make_uint2(l0, l1);
        xs[row][c4 + 0] = v.x; xs[row][c4 + 1] = v.y;
        xs[row][c4 + 2] = v.z; xs[row][c4 + 3] = v.w;
    }
    __syncthreads();
    #pragma unroll
    for (int p = 0; p < 4; p++){
        int cl = p * 16 + (t >> 4);
        int n4 = (t & 15) * 4;
        float v0 = xs[n4][cl], v1 = xs[n4+1][cl], v2 = xs[n4+2][cl], v3 = xs[n4+3][cl];
        uint32_t h0, l0, h1, l1;
        split_pair(v0, v1, h0, l0);
        split_pair(v2, v3, h1, l1);
        size_t di = ((size_t)b * CC + c0 + cl) * NN + n0 + n4;
        *(uint2*)(g_xThi + di) = make_uint2(h0, h1);
        *(uint2*)(g_xTlo + di) = make_uint2(l0, l1);
    }
}
__global__ void k_cvt_w(const float* __restrict__ Wq, const float* __restrict__ Wv,
                        const float* __restrict__ Wt){
    // side duty: zero colsum accumulators (softmax atomics add into them later)
    if (blockIdx.x < 16) g_colsum[blockIdx.x * 256 + threadIdx.x] = 0.f;
    int idx = blockIdx.x * blockDim.x + threadIdx.x;
    int which = idx >> 16, rem = idx & 65535;
    const float* s = (which == 0) ? Wq : (which == 1) ? Wv : Wt;
    split_store(g_Whi, g_Wlo, idx, s[rem]);
}

// ---------------- KT1: v^T (side stream) ------------------------------------
__global__ void __launch_bounds__(256, 2)
kt1(const float* __restrict__ bv){
    extern __shared__ char smem[];
    int b = blockIdx.z;
    size_t xoff = (size_t)b * NN * CC;
    int mBase = blockIdx.x * 128, nBase = blockIdx.y * 64;
    const bf16* Ahi = g_xhi + xoff + (size_t)mBase * CC;
    const bf16* Alo = g_xlo + xoff + (size_t)mBase * CC;
    const bf16* Bhi = g_Whi + CC * CC + nBase * CC;
    const bf16* Blo = g_Wlo + CC * CC + nBase * CC;
    float acc[2][4][4] = {};
    gemm_main(smem, Ahi, Alo, CC, Bhi, Blo, CC, 4, acc);

    int tid = threadIdx.x, lane = tid & 31, wid = tid >> 5;
    int warpM = wid & 3, warpN = wid >> 2;
    int gr = lane >> 2, gc = (lane & 3) * 2;
    #pragma unroll
    for (int mf = 0; mf < 2; mf++)
        #pragma unroll
        for (int nf = 0; nf < 4; nf++){
            float* c = acc[mf][nf];
            int row0 = warpM * 32 + mf * 16 + gr;
            int col  = warpN * 32 + nf * 8 + gc;
            #pragma unroll
            for (int h = 0; h < 2; h++){
                int n = mBase + row0 + h * 8, o = nBase + col;
                size_t di = ((size_t)b * NN + n) * CC + o;
                uint32_t hi, lo;
                split_pair(c[2*h] + bv[o], c[2*h+1] + bv[o+1], hi, lo);
                *(uint32_t*)(g_vhi + di) = hi;
                *(uint32_t*)(g_vlo + di) = lo;
            }
        }
}

// ---------------- KTG: G = x^T x (split-K x3, symmetric: 6 of 8 tiles) ------
// 6 tiles x 3 K-splits x 16 batches = 288 CTAs = one full wave at 2 CTAs/SM
__constant__ int c_tileC[6] = {0, 0, 0, 0, 128, 128};
__constant__ int c_tileD[6] = {0, 64, 128, 192, 128, 192};
__constant__ int c_ks0[3] = {0, 22, 43};    // chunk start (64-wide chunks)
__constant__ int c_ksn[3] = {22, 21, 21};   // chunk count
__global__ void __launch_bounds__(256, 2)
ktG(){
    extern __shared__ char smem[];
    int b = blockIdx.z / 3, ks = blockIdx.z % 3;
    int cBase = c_tileC[blockIdx.x], dBase = c_tileD[blockIdx.x];
    size_t kOff = (size_t)c_ks0[ks] * 64;
    int nch = c_ksn[ks];
    const bf16* Ah = g_xThi + ((size_t)b * CC + cBase) * NN + kOff;
    const bf16* Al = g_xTlo + ((size_t)b * CC + cBase) * NN + kOff;
    const bf16* Bh = g_xThi + ((size_t)b * CC + dBase) * NN + kOff;
    const bf16* Bl = g_xTlo + ((size_t)b * CC + dBase) * NN + kOff;
    float acc[2][4][4] = {};
    gemm_main(smem, Ah, Al, NN, Bh, Bl, NN, nch, acc);

    int tid = threadIdx.x, lane = tid & 31, wid = tid >> 5;
    int warpM = wid & 3, warpN = wid >> 2;
    int gr = lane >> 2, gc = (lane & 3) * 2;
    float* dst = g_Gp + ((size_t)(ks * BB + b)) * CC * CC;
    #pragma unroll
    for (int mf = 0; mf < 2; mf++)
        #pragma unroll
        for (int nf = 0; nf < 4; nf++){
            float* c = acc[mf][nf];
            int row0 = warpM * 32 + mf * 16 + gr;
            int col  = warpN * 32 + nf * 8 + gc;
            #pragma unroll
            for (int h = 0; h < 2; h++)
                *(float2*)(dst + (size_t)(cBase + row0 + h*8) * CC + dBase + col)
                    = make_float2(c[2*h], c[2*h+1]);
        }
}
// sum split-K partials; mirror the uncomputed lower-left quadrant (r>=128,c<128)
__global__ void k_gsum(){
    size_t i = ((size_t)blockIdx.x * blockDim.x + threadIdx.x) * 4;
    const size_t S = (size_t)BB * CC * CC;
    int b  = (int)(i >> 16);
    int rc = (int)(i & 65535);
    int r = rc >> 8, c0 = rc & 255;
    float v[4];
    if (r >= 128 && c0 < 128){
        #pragma unroll
        for (int j = 0; j < 4; j++){
            size_t src = (size_t)b * CC * CC + (size_t)(c0 + j) * CC + r;  // transposed
            v[j] = g_Gp[src] + g_Gp[S + src] + g_Gp[2*S + src];
        }
    } else {
        float4 a = *(const float4*)(g_Gp + i);
        float4 bb = *(const float4*)(g_Gp + S + i);
        float4 cc = *(const float4*)(g_Gp + 2*S + i);
        v[0] = a.x+bb.x+cc.x; v[1] = a.y+bb.y+cc.y;
        v[2] = a.z+bb.z+cc.z; v[3] = a.w+bb.w+cc.w;
    }
    uint32_t h0,l0,h1,l1;
    split_pair(v[0],v[1],h0,l0); split_pair(v[2],v[3],h1,l1);
    *(uint2*)(g_Ghi + i) = make_uint2(h0,h1);
    *(uint2*)(g_Glo + i) = make_uint2(l0,l1);
}

// ---------------- small square GEMMs (K=256) --------------------------------
// mode 0: E1 = Wq.G ; mode 1: E = E1.Wq^T (fp32) ; mode 2: -M = -(Wt.attS) split
__global__ void __launch_bounds__(256, 2)
ksq(int mode){
    extern __shared__ char smem[];
    int b = blockIdx.z;
    int mBase = blockIdx.y * 128, nBase = blockIdx.x * 64;
    size_t boff = (size_t)b * CC * CC;
    const bf16 *Ah, *Al, *Bh, *Bl;
    if (mode == 0){
        Ah = g_Whi + mBase * CC;        Al = g_Wlo + mBase * CC;
        Bh = g_Ghi + boff + nBase * CC; Bl = g_Glo + boff + nBase * CC;
    } else if (mode == 1){
        Ah = g_E1hi + boff + mBase * CC; Al = g_E1lo + boff + mBase * CC;
        Bh = g_Whi + nBase * CC;         Bl = g_Wlo + nBase * CC;
    } else {
        Ah = g_Whi + 2*CC*CC + mBase * CC; Al = g_Wlo + 2*CC*CC + mBase * CC;
        Bh = g_atthi + boff + nBase * CC;  Bl = g_attlo + boff + nBase * CC;
    }
    float acc[2][4][4] = {};
    gemm_main(smem, Ah, Al, CC, Bh, Bl, CC, 4, acc);

    int tid = threadIdx.x, lane = tid & 31, wid = tid >> 5;
    int warpM = wid & 3, warpN = wid >> 2;
    int gr = lane >> 2, gc = (lane & 3) * 2;
    #pragma unroll
    for (int mf = 0; mf < 2; mf++)
        #pragma unroll
        for (int nf = 0; nf < 4; nf++){
            float* c = acc[mf][nf];
            int row0 = warpM * 32 + mf * 16 + gr;
            int col  = warpN * 32 + nf * 8 + gc;
            #pragma unroll
            for (int h = 0; h < 2; h++){
                size_t di = boff + (size_t)(mBase + row0 + h*8) * CC + nBase + col;
                if (mode == 1){
                    *(float2*)(g_att + di) = make_float2(c[2*h], c[2*h+1]);
                } else if (mode == 0){
                    uint32_t hi, lo;
                    split_pair(c[2*h], c[2*h+1], hi, lo);
                    *(uint32_t*)(g_E1hi + di) = hi; *(uint32_t*)(g_E1lo + di) = lo;
                } else {
                    uint32_t hi, lo;
                    split_pair(-c[2*h], -c[2*h+1], hi, lo);   // store NEGATED M
                    *(uint32_t*)(g_Mhi + di) = hi; *(uint32_t*)(g_Mlo + di) = lo;
                }
            }
        }
}

// ---------------- softmax (+ fused colsum) / att scaling --------------------
__global__ void k_softmax(){
    size_t row = blockIdx.x;
    float* p = g_att + row * CC;
    int t = threadIdx.x;
    float v = p[t];
    __shared__ float red[256];
    red[t] = v; __syncthreads();
    for (int s = 128; s > 0; s >>= 1){ if (t < s) red[t] = fmaxf(red[t], red[t+s]); __syncthreads(); }
    float mx = red[0]; __syncthreads();
    float e = __expf(v - mx);
    red[t] = e; __syncthreads();
    for (int s = 128; s > 0; s >>= 1){ if (t < s) red[t] += red[t+s]; __syncthreads(); }
    float val = e / red[0];
    p[t] = val;
    int b = (int)(row >> 8);
    atomicAdd(&g_colsum[b * CC + t], val);      // fused column sum
}
// attS = att / (1e-9 + colsum[d]), split to bf16; also zeroes BN accumulators
__global__ void k_scaleAtt(){
    if (blockIdx.x == 0){ g_bns[threadIdx.x] = 0.f; g_bnq[threadIdx.x] = 0.f; }
    size_t i = ((size_t)blockIdx.x * blockDim.x + threadIdx.x) * 4;
    int b = (int)(i >> 16);
    int d = (int)(i & 255);
    float4 a  = *(const float4*)(g_att + i);
    float4 cs = *(const float4*)(g_colsum + b * CC + d);
    float v0 = a.x / (1e-9f + cs.x), v1 = a.y / (1e-9f + cs.y);
    float v2 = a.z / (1e-9f + cs.z), v3 = a.w / (1e-9f + cs.w);
    uint32_t h0,l0,h1,l1;
    split_pair(v0,v1,h0,l0); split_pair(v2,v3,h1,l1);
    *(uint2*)(g_atthi + i) = make_uint2(h0,h1);
    *(uint2*)(g_attlo + i) = make_uint2(l0,l1);
}

// ---------------- KT6: t = [x|v].[Wt|-M]^T + bt  (K=512) + fused BN sums ----
__global__ void __launch_bounds__(256, 2)
kt6(const float* __restrict__ bt){
    extern __shared__ char smem[];
    int b = blockIdx.z;
    int mBase = blockIdx.x * 128;   // n
    int oBase = blockIdx.y * 64;    // o
    size_t nrow = (size_t)b * NN + mBase;
    size_t boff = (size_t)b * CC * CC;
    const bf16* Ah[2] = { g_xhi + nrow * CC, g_vhi + nrow * CC };
    const bf16* Al[2] = { g_xlo + nrow * CC, g_vlo + nrow * CC };
    const bf16* Bh[2] = { g_Whi + 2*CC*CC + oBase * CC, g_Mhi + boff + oBase * CC };
    const bf16* Bl[2] = { g_Wlo + 2*CC*CC + oBase * CC, g_Mlo + boff + oBase * CC };

    int tid = threadIdx.x, lane = tid & 31, wid = tid >> 5;
    int warpM = wid & 3, warpN = wid >> 2;
    uint32_t sb0 = smem_u32(smem);
    float acc[2][4][4] = {};

    ld_chunk(smem, 0, tid, Ah[0], Al[0], Bh[0], Bl[0], CC, CC, 0);
    for (int cc = 0; cc < 8; cc++){
        if (cc + 1 < 8){
            int s = (cc + 1) >> 2;
            ld_chunk(smem, (cc + 1) & 1, tid, Ah[s], Al[s], Bh[s], Bl[s],
                     CC, CC, ((cc + 1) & 3) * 64);
            asm volatile("cp.async.wait_group 1;" ::: "memory");
        } else {
            asm volatile("cp.async.wait_group 0;" ::: "memory");
        }
        __syncthreads();
        compute_chunk(sb0 + (cc & 1) * STAGE, lane, warpM, warpN, acc);
        __syncthreads();
    }

    __shared__ float bn_s[64], bn_q[64];
    if (tid < 64){ bn_s[tid] = 0.f; bn_q[tid] = 0.f; }
    __syncthreads();

    int gr = lane >> 2, gc = (lane & 3) * 2;
    float sA[4][2], qA[4][2];
    #pragma unroll
    for (int nf = 0; nf < 4; nf++){
        sA[nf][0] = sA[nf][1] = qA[nf][0] = qA[nf][1] = 0.f;
        int col = warpN * 32 + nf * 8 + gc;
        int o = oBase + col;
        float b0 = bt[o], b1 = bt[o + 1];
        #pragma unroll
        for (int mf = 0; mf < 2; mf++){
            float* c = acc[mf][nf];
            int row0 = warpM * 32 + mf * 16 + gr;
            #pragma unroll
            for (int h = 0; h < 2; h++){
                int n = mBase + row0 + h * 8;
                float v0 = c[2*h] + b0, v1 = c[2*h+1] + b1;
                *(float2*)(g_t + ((size_t)b * NN + n) * CC + o) = make_float2(v0, v1);
                sA[nf][0] += v0;       sA[nf][1] += v1;
                qA[nf][0] += v0 * v0;  qA[nf][1] += v1 * v1;
            }
        }
    }
    #pragma unroll
    for (int nf = 0; nf < 4; nf++){
        #pragma unroll
        for (int st = 4; st < 32; st <<= 1){
            sA[nf][0] += __shfl_down_sync(0xffffffffu, sA[nf][0], st);
            sA[nf][1] += __shfl_down_sync(0xffffffffu, sA[nf][1], st);
            qA[nf][0] += __shfl_down_sync(0xffffffffu, qA[nf][0], st);
            qA[nf][1] += __shfl_down_sync(0xffffffffu, qA[nf][1], st);
        }
    }
    if (lane < 4){
        #pragma unroll
        for (int nf = 0; nf < 4; nf++){
            int colL = warpN * 32 + nf * 8 + lane * 2;
            atomicAdd(&bn_s[colL],     sA[nf][0]);
            atomicAdd(&bn_s[colL + 1], sA[nf][1]);
            atomicAdd(&bn_q[colL],     qA[nf][0]);
            atomicAdd(&bn_q[colL + 1], qA[nf][1]);
        }
    }
    __syncthreads();
    if (tid < 64){
        atomicAdd(&g_bns[oBase + tid], bn_s[tid]);
        atomicAdd(&g_bnq[oBase + tid], bn_q[tid]);
    }
}

// ---------------- BN finalize + final --------------------------------------
__global__ void k_bnfin(const float* __restrict__ gamma, const float* __restrict__ beta){
    int o = threadIdx.x;
    float inv = 1.0f / (float)(BB * NN);
    float mean = g_bns[o] * inv;
    float var  = g_bnq[o] * inv - mean * mean;
    float rstd = rsqrtf(var + 1e-5f);
    float sc = gamma[o] * rstd;
    g_scale[o] = sc;
    g_shift[o] = beta[o] - mean * sc;
}
__global__ void k_final(const float* __restrict__ x, float* __restrict__ out){
    size_t i = ((size_t)blockIdx.x * blockDim.x + threadIdx.x) * 4;
    int o = (int)(i & (CC - 1));
    float4 t4 = *(const float4*)(g_t + i);
    float4 x4 = *(const float4*)(x + i);
    float4 sc = *(const float4*)(g_scale + o);
    float4 sh = *(const float4*)(g_shift + o);
    float4 r;
    r.x = x4.x + fmaxf(fmaf(t4.x, sc.x, sh.x), 0.f);
    r.y = x4.y + fmaxf(fmaf(t4.y, sc.y, sh.y), 0.f);
    r.z = x4.z + fmaxf(fmaf(t4.z, sc.z, sh.z), 0.f);
    r.w = x4.w + fmaxf(fmaf(t4.w, sc.w, sh.w), 0.f);
    *(float4*)(out + i) = r;
}

// ---------------- launch ----------------------------------------------------
extern "C" void kernel_launch(void* const* d_in, const int* in_sizes, int n_in,
                              void* d_out, int out_size){
    (void)in_sizes; (void)n_in; (void)out_size;
    const float* x     = (const float*)d_in[1];
    const float* Wq    = (const float*)d_in[2];
    const float* Wv    = (const float*)d_in[3];
    const float* bv    = (const float*)d_in[4];
    const float* Wt    = (const float*)d_in[5];
    const float* bt    = (const float*)d_in[6];
    const float* gamma = (const float*)d_in[7];
    const float* beta  = (const float*)d_in[8];
    float* out = (float*)d_out;

    static cudaStream_t s2 = nullptr;
    static cudaEvent_t eFork = nullptr, eJoin = nullptr;
    if (!s2){
        cudaStreamCreateWithFlags(&s2, cudaStreamNonBlocking);
        cudaEventCreateWithFlags(&eFork, cudaEventDisableTiming);
        cudaEventCreateWithFlags(&eJoin, cudaEventDisableTiming);
        cudaFuncSetAttribute(kt1, cudaFuncAttributeMaxDynamicSharedMemorySize, SDYN);
        cudaFuncSetAttribute(ktG, cudaFuncAttributeMaxDynamicSharedMemorySize, SDYN);
        cudaFuncSetAttribute(ksq, cudaFuncAttributeMaxDynamicSharedMemorySize, SDYN);
        cudaFuncSetAttribute(kt6, cudaFuncAttributeMaxDynamicSharedMemorySize, SDYN);
    }

    k_cvt_x  <<<dim3(64, 4, BB), 256>>>(x);
    k_cvt_w  <<<768, 256>>>(Wq, Wv, Wt);

    // fork: v-projection runs concurrently with the attention chain
    cudaEventRecord(eFork, 0);
    cudaStreamWaitEvent(s2, eFork, 0);
    kt1      <<<dim3(32, 4, BB), 256, SDYN, s2>>>(bv);
    cudaEventRecord(eJoin, s2);

    ktG      <<<dim3(6, 1, 3*BB), 256, SDYN>>>();
    k_gsum   <<<1024, 256>>>();
    ksq      <<<dim3(4, 2, BB), 256, SDYN>>>(0);
    ksq      <<<dim3(4, 2, BB), 256, SDYN>>>(1);
    k_softmax<<<BB*CC, 256>>>();
    k_scaleAtt<<<1024, 256>>>();
    ksq      <<<dim3(4, 2, BB), 256, SDYN>>>(2);

    cudaStreamWaitEvent(0, eJoin, 0);     // join before fused kt6
    kt6      <<<dim3(32, 4, BB), 256, SDYN>>>(bt);
    k_bnfin  <<<1, 256>>>(gamma, beta);
    k_final  <<<16384, 256>>>(x, out);
}

// round 10
// speedup vs baseline: 1.5190x; 1.4655x over previous
#include <cuda_runtime.h>
#include <cuda_bf16.h>
#include <cstdint>

#define BB 16
#define NN 4096
#define CC 256

using bf16 = __nv_bfloat16;

// ---------------- scratch (device globals; no allocation allowed) ----------
__device__ __align__(16) bf16  g_xhi[(size_t)BB*NN*CC];   // x split, [B][N][C]
__device__ __align__(16) bf16  g_xlo[(size_t)BB*NN*CC];
__device__ __align__(16) bf16  g_xThi[(size_t)BB*CC*NN];  // x^T split, [B][C][N]
__device__ __align__(16) bf16  g_xTlo[(size_t)BB*CC*NN];
__device__ __align__(16) bf16  g_Whi[3*CC*CC];            // Wq, Wv, Wt split
__device__ __align__(16) bf16  g_Wlo[3*CC*CC];
__device__ __align__(16) bf16  g_WvThi[CC*CC];            // Wv^T split  [k][c]
__device__ __align__(16) bf16  g_WvTlo[CC*CC];
__device__ float g_t[(size_t)BB*NN*CC];     // pre-BN t, [B][N][C]
__device__ float g_Gp[(size_t)3*BB*CC*CC];  // split-K partials of G (3 ways)
__device__ __align__(16) bf16  g_Ghi[(size_t)BB*CC*CC];
__device__ __align__(16) bf16  g_Glo[(size_t)BB*CC*CC];
__device__ __align__(16) bf16  g_E1hi[(size_t)BB*CC*CC];
__device__ __align__(16) bf16  g_E1lo[(size_t)BB*CC*CC];
__device__ float g_att[(size_t)BB*CC*CC];
__device__ __align__(16) bf16  g_atthi[(size_t)BB*CC*CC]; // att/colsum split
__device__ __align__(16) bf16  g_attlo[(size_t)BB*CC*CC];
__device__ __align__(16) bf16  g_Mhi[(size_t)BB*CC*CC];   // M split [o][c]
__device__ __align__(16) bf16  g_Mlo[(size_t)BB*CC*CC];
__device__ __align__(16) bf16  g_Fhi[(size_t)BB*CC*CC];   // Weff = Wt - M.Wv split
__device__ __align__(16) bf16  g_Flo[(size_t)BB*CC*CC];
__device__ float g_beff[BB*CC];             // bt - M.bv
__device__ float g_colsum[BB*CC];
__device__ float g_bns[CC];                 // fused BN Σt per channel
__device__ float g_bnq[CC];                 // fused BN Σt² per channel
__device__ float g_scale[CC];
__device__ float g_shift[CC];

// Stage: Ahi(16K) Alo(16K) Bhi(8K) Blo(8K) = 48KB; 2 stages
#define ST_ALO 16384
#define ST_BHI 32768
#define ST_BLO 40960
#define STAGE  49152
#define SDYN   (2*STAGE)

// ---------------- helpers ---------------------------------------------------
__device__ __forceinline__ uint32_t smem_u32(const void* p){
    uint32_t a;
    asm("{ .reg .u64 t; cvta.to.shared.u64 t, %1; cvt.u32.u64 %0, t; }" : "=r"(a) : "l"(p));
    return a;
}
__device__ __forceinline__ uint32_t sw128(uint32_t o){ return o ^ ((o >> 3) & 0x70); }

__device__ __forceinline__ void ldm4(uint32_t* r, uint32_t addr){
    asm volatile("ldmatrix.sync.aligned.m8n8.x4.shared.b16 {%0,%1,%2,%3}, [%4];"
        : "=r"(r[0]), "=r"(r[1]), "=r"(r[2]), "=r"(r[3]) : "r"(addr));
}
__device__ __forceinline__ void mma_bf16(float* c, const uint32_t* a, const uint32_t* b){
    asm volatile("mma.sync.aligned.m16n8k16.row.col.f32.bf16.bf16.f32 "
        "{%0,%1,%2,%3}, {%4,%5,%6,%7}, {%8,%9}, {%0,%1,%2,%3};"
        : "+f"(c[0]), "+f"(c[1]), "+f"(c[2]), "+f"(c[3])
        : "r"(a[0]), "r"(a[1]), "r"(a[2]), "r"(a[3]), "r"(b[0]), "r"(b[1]));
}
__device__ __forceinline__ void cpa16(uint32_t dst, const void* src){
    asm volatile("cp.async.cg.shared.global [%0], [%1], 16;" :: "r"(dst), "l"(src));
}
__device__ __forceinline__ void split_store(bf16* hi, bf16* lo, size_t i, float v){
    bf16 h = __float2bfloat16(v);
    hi[i] = h;
    lo[i] = __float2bfloat16(v - __bfloat162float(h));
}
__device__ __forceinline__ void split_pair(float v0, float v1, uint32_t& hi, uint32_t& lo){
    bf16 h0 = __float2bfloat16(v0), h1 = __float2bfloat16(v1);
    float r0 = v0 - __bfloat162float(h0), r1 = v1 - __bfloat162float(h1);
    __nv_bfloat162 ph; ph.x = h0; ph.y = h1;
    __nv_bfloat162 pl = __floats2bfloat162_rn(r0, r1);
    hi = *(uint32_t*)&ph;
    lo = *(uint32_t*)&pl;
}

// ---------------------------------------------------------------------------
// Split-bf16 128(M)x64(N) GEMM building blocks, cp.async 2-stage, 2 CTAs/SM.
// ---------------------------------------------------------------------------
__device__ __forceinline__ void ld_chunk(char* smem, int stage, int tid,
        const bf16* __restrict__ Ahi, const bf16* __restrict__ Alo,
        const bf16* __restrict__ Bhi, const bf16* __restrict__ Blo,
        int ldA, int ldB, int c0){
    uint32_t sbase = smem_u32(smem) + stage * STAGE;
    #pragma unroll
    for (int i = 0; i < 4; i++){           // A: 128 rows x 8 segs
        int g = tid + i * 256;
        int row = g >> 3, cg = g & 7;
        uint32_t so = sw128((uint32_t)(row * 128 + cg * 16));
        size_t ga = (size_t)row * ldA + c0 + cg * 8;
        cpa16(sbase + so,          Ahi + ga);
        cpa16(sbase + ST_ALO + so, Alo + ga);
    }
    #pragma unroll
    for (int i = 0; i < 2; i++){           // B: 64 rows x 8 segs
        int g = tid + i * 256;
        int row = g >> 3, cg = g & 7;
        uint32_t so = sw128((uint32_t)(row * 128 + cg * 16));
        size_t gb = (size_t)row * ldB + c0 + cg * 8;
        cpa16(sbase + ST_BHI + so, Bhi + gb);
        cpa16(sbase + ST_BLO + so, Blo + gb);
    }
    asm volatile("cp.async.commit_group;" ::: "memory");
}

__device__ __forceinline__ void compute_chunk(uint32_t sb, int lane,
        int warpM, int warpN, float acc[2][4][4]){
    #pragma unroll
    for (int ks = 0; ks < 4; ks++){
        uint32_t ahi[2][4], alo[2][4];
        #pragma unroll
        for (int mf = 0; mf < 2; mf++){
            int row = warpM * 32 + mf * 16 + (lane & 15);
            uint32_t off = sw128((uint32_t)(row * 128 + ks * 32 + (lane >> 4) * 16));
            ldm4(ahi[mf], sb + off);
            ldm4(alo[mf], sb + ST_ALO + off);
        }
        #pragma unroll
        for (int ng = 0; ng < 2; ng++){
            int rowb = warpN * 32 + ng * 16 + (lane & 15);
            uint32_t off = sw128((uint32_t)(rowb * 128 + ks * 32 + (lane >> 4) * 16));
            uint32_t bh[4], bl[4];
            ldm4(bh, sb + ST_BHI + off);
            ldm4(bl, sb + ST_BLO + off);
            uint32_t bh0[2] = {bh[0], bh[2]}, bh1[2] = {bh[1], bh[3]};
            uint32_t bl0[2] = {bl[0], bl[2]}, bl1[2] = {bl[1], bl[3]};
            #pragma unroll
            for (int mf = 0; mf < 2; mf++){
                mma_bf16(acc[mf][ng*2],     ahi[mf], bh0);
                mma_bf16(acc[mf][ng*2],     ahi[mf], bl0);
                mma_bf16(acc[mf][ng*2],     alo[mf], bh0);
                mma_bf16(acc[mf][ng*2 + 1], ahi[mf], bh1);
                mma_bf16(acc[mf][ng*2 + 1], ahi[mf], bl1);
                mma_bf16(acc[mf][ng*2 + 1], alo[mf], bh1);
            }
        }
    }
}

__device__ __forceinline__ void gemm_main(char* smem,
        const bf16* __restrict__ Ahi, const bf16* __restrict__ Alo, int ldA,
        const bf16* __restrict__ Bhi, const bf16* __restrict__ Blo, int ldB,
        int nChunks, float acc[2][4][4])
{
    int tid = threadIdx.x, lane = tid & 31, wid = tid >> 5;
    int warpM = wid & 3, warpN = wid >> 2;
    uint32_t sb0 = smem_u32(smem);

    ld_chunk(smem, 0, tid, Ahi, Alo, Bhi, Blo, ldA, ldB, 0);
    for (int cc = 0; cc < nChunks; cc++){
        if (cc + 1 < nChunks){
            ld_chunk(smem, (cc + 1) & 1, tid, Ahi, Alo, Bhi, Blo, ldA, ldB, (cc + 1) * 64);
            asm volatile("cp.async.wait_group 1;" ::: "memory");
        } else {
            asm volatile("cp.async.wait_group 0;" ::: "memory");
        }
        __syncthreads();
        compute_chunk(sb0 + (cc & 1) * STAGE, lane, warpM, warpN, acc);
        __syncthreads();
    }
}

// ---------------- conversion: x -> split x AND split x^T --------------------
__global__ void __launch_bounds__(256) k_cvt_x(const float* __restrict__ x){
    int b = blockIdx.z, n0 = blockIdx.x * 64, c0 = blockIdx.y * 64;
    __shared__ float xs[64][65];
    int t = threadIdx.x;
    const float* xb = x + ((size_t)b * NN + n0) * CC + c0;
    #pragma unroll
    for (int p = 0; p < 4; p++){
        int row = p * 16 + (t >> 4);
        int c4  = (t & 15) * 4;
        float4 v = *(const float4*)(xb + (size_t)row * CC + c4);
        uint32_t h0, l0, h1, l1;
        split_pair(v.x, v.y, h0, l0);
        split_pair(v.z, v.w, h1, l1);
        size_t di = ((size_t)b * NN + n0 + row) * CC + c0 + c4;
        *(uint2*)(g_xhi + di) = make_uint2(h0, h1);
        *(uint2*)(g_xlo + di) = make_uint2(l0, l1);
        xs[row][c4 + 0] = v.x; xs[row][c4 + 1] = v.y;
        xs[row][c4 + 2] = v.z; xs[row][c4 + 3] = v.w;
    }
    __syncthreads();
    #pragma unroll
    for (int p = 0; p < 4; p++){
        int cl = p * 16 + (t >> 4);
        int n4 = (t & 15) * 4;
        float v0 = xs[n4][cl], v1 = xs[n4+1][cl], v2 = xs[n4+2][cl], v3 = xs[n4+3][cl];
        uint32_t h0, l0, h1, l1;
        split_pair(v0, v1, h0, l0);
        split_pair(v2, v3, h1, l1);
        size_t di = ((size_t)b * CC + c0 + cl) * NN + n0 + n4;
        *(uint2*)(g_xThi + di) = make_uint2(h0, h1);
        *(uint2*)(g_xTlo + di) = make_uint2(l0, l1);
    }
}
__global__ void k_cvt_w(const float* __restrict__ Wq, const float* __restrict__ Wv,
                        const float* __restrict__ Wt){
    // side duty: zero colsum accumulators (softmax atomics add into them later)
    if (blockIdx.x < 16) g_colsum[blockIdx.x * 256 + threadIdx.x] = 0.f;
    int idx = blockIdx.x * blockDim.x + threadIdx.x;
    int which = idx >> 16, rem = idx & 65535;
    const float* s = (which == 0) ? Wq : (which == 1) ? Wv : Wt;
    float v = s[rem];
    split_store(g_Whi, g_Wlo, idx, v);
    if (which == 1){
        int o = rem >> 8, c = rem & 255;          // Wv[o][c] -> WvT[c][o]
        split_store(g_WvThi, g_WvTlo, (size_t)c * CC + o, v);
    }
}

// ---------------- KTG: G = x^T x (split-K x3, symmetric: 6 of 8 tiles) ------
// 6 tiles x 3 K-splits x 16 batches = 288 CTAs = one full wave at 2 CTAs/SM
__constant__ int c_tileC[6] = {0, 0, 0, 0, 128, 128};
__constant__ int c_tileD[6] = {0, 64, 128, 192, 128, 192};
__constant__ int c_ks0[3] = {0, 22, 43};    // chunk start (64-wide chunks)
__constant__ int c_ksn[3] = {22, 21, 21};   // chunk count
__global__ void __launch_bounds__(256, 2)
ktG(){
    extern __shared__ char smem[];
    int b = blockIdx.z / 3, ks = blockIdx.z % 3;
    int cBase = c_tileC[blockIdx.x], dBase = c_tileD[blockIdx.x];
    size_t kOff = (size_t)c_ks0[ks] * 64;
    int nch = c_ksn[ks];
    const bf16* Ah = g_xThi + ((size_t)b * CC + cBase) * NN + kOff;
    const bf16* Al = g_xTlo + ((size_t)b * CC + cBase) * NN + kOff;
    const bf16* Bh = g_xThi + ((size_t)b * CC + dBase) * NN + kOff;
    const bf16* Bl = g_xTlo + ((size_t)b * CC + dBase) * NN + kOff;
    float acc[2][4][4] = {};
    gemm_main(smem, Ah, Al, NN, Bh, Bl, NN, nch, acc);

    int tid = threadIdx.x, lane = tid & 31, wid = tid >> 5;
    int warpM = wid & 3, warpN = wid >> 2;
    int gr = lane >> 2, gc = (lane & 3) * 2;
    float* dst = g_Gp + ((size_t)(ks * BB + b)) * CC * CC;
    #pragma unroll
    for (int mf = 0; mf < 2; mf++)
        #pragma unroll
        for (int nf = 0; nf < 4; nf++){
            float* c = acc[mf][nf];
            int row0 = warpM * 32 + mf * 16 + gr;
            int col  = warpN * 32 + nf * 8 + gc;
            #pragma unroll
            for (int h = 0; h < 2; h++)
                *(float2*)(dst + (size_t)(cBase + row0 + h*8) * CC + dBase + col)
                    = make_float2(c[2*h], c[2*h+1]);
        }
}
// sum split-K partials; mirror the uncomputed lower-left quadrant (r>=128,c<128)
__global__ void k_gsum(){
    size_t i = ((size_t)blockIdx.x * blockDim.x + threadIdx.x) * 4;
    const size_t S = (size_t)BB * CC * CC;
    int b  = (int)(i >> 16);
    int rc = (int)(i & 65535);
    int r = rc >> 8, c0 = rc & 255;
    float v[4];
    if (r >= 128 && c0 < 128){
        #pragma unroll
        for (int j = 0; j < 4; j++){
            size_t src = (size_t)b * CC * CC + (size_t)(c0 + j) * CC + r;  // transposed
            v[j] = g_Gp[src] + g_Gp[S + src] + g_Gp[2*S + src];
        }
    } else {
        float4 a = *(const float4*)(g_Gp + i);
        float4 bb = *(const float4*)(g_Gp + S + i);
        float4 cc = *(const float4*)(g_Gp + 2*S + i);
        v[0] = a.x+bb.x+cc.x; v[1] = a.y+bb.y+cc.y;
        v[2] = a.z+bb.z+cc.z; v[3] = a.w+bb.w+cc.w;
    }
    uint32_t h0,l0,h1,l1;
    split_pair(v[0],v[1],h0,l0); split_pair(v[2],v[3],h1,l1);
    *(uint2*)(g_Ghi + i) = make_uint2(h0,h1);
    *(uint2*)(g_Glo + i) = make_uint2(l0,l1);
}

// ---------------- small square GEMMs (K=256) --------------------------------
// mode 0: E1 = Wq.G            -> split E1
// mode 1: E  = E1.Wq^T         -> fp32 g_att
// mode 2: M  = Wt.attS         -> split M
// mode 3: Weff = Wt - M.Wv     -> split F   (B operand = Wv^T rows k)
__global__ void __launch_bounds__(256, 2)
ksq(int mode, const float* __restrict__ Wt){
    extern __shared__ char smem[];
    int b = blockIdx.z;
    int mBase = blockIdx.y * 128, nBase = blockIdx.x * 64;
    size_t boff = (size_t)b * CC * CC;
    const bf16 *Ah, *Al, *Bh, *Bl;
    if (mode == 0){
        Ah = g_Whi + mBase * CC;        Al = g_Wlo + mBase * CC;
        Bh = g_Ghi + boff + nBase * CC; Bl = g_Glo + boff + nBase * CC;
    } else if (mode == 1){
        Ah = g_E1hi + boff + mBase * CC; Al = g_E1lo + boff + mBase * CC;
        Bh = g_Whi + nBase * CC;         Bl = g_Wlo + nBase * CC;
    } else if (mode == 2){
        Ah = g_Whi + 2*CC*CC + mBase * CC; Al = g_Wlo + 2*CC*CC + mBase * CC;
        Bh = g_atthi + boff + nBase * CC;  Bl = g_attlo + boff + nBase * CC;
    } else {
        Ah = g_Mhi + boff + mBase * CC;  Al = g_Mlo + boff + mBase * CC;
        Bh = g_WvThi + nBase * CC;       Bl = g_WvTlo + nBase * CC;
    }
    float acc[2][4][4] = {};
    gemm_main(smem, Ah, Al, CC, Bh, Bl, CC, 4, acc);

    int tid = threadIdx.x, lane = tid & 31, wid = tid >> 5;
    int warpM = wid & 3, warpN = wid >> 2;
    int gr = lane >> 2, gc = (lane & 3) * 2;
    #pragma unroll
    for (int mf = 0; mf < 2; mf++)
        #pragma unroll
        for (int nf = 0; nf < 4; nf++){
            float* c = acc[mf][nf];
            int row0 = warpM * 32 + mf * 16 + gr;
            int col  = warpN * 32 + nf * 8 + gc;
            #pragma unroll
            for (int h = 0; h < 2; h++){
                int rr = mBase + row0 + h*8, kk = nBase + col;
                size_t di = boff + (size_t)rr * CC + kk;
                if (mode == 1){
                    *(float2*)(g_att + di) = make_float2(c[2*h], c[2*h+1]);
                } else if (mode == 0){
                    uint32_t hi, lo;
                    split_pair(c[2*h], c[2*h+1], hi, lo);
                    *(uint32_t*)(g_E1hi + di) = hi; *(uint32_t*)(g_E1lo + di) = lo;
                } else if (mode == 2){
                    uint32_t hi, lo;
                    split_pair(c[2*h], c[2*h+1], hi, lo);
                    *(uint32_t*)(g_Mhi + di) = hi; *(uint32_t*)(g_Mlo + di) = lo;
                } else {
                    float w0 = Wt[(size_t)rr * CC + kk];
                    float w1 = Wt[(size_t)rr * CC + kk + 1];
                    uint32_t hi, lo;
                    split_pair(w0 - c[2*h], w1 - c[2*h+1], hi, lo);
                    *(uint32_t*)(g_Fhi + di) = hi; *(uint32_t*)(g_Flo + di) = lo;
                }
            }
        }
}

// ---------------- softmax (+ fused colsum) / att scaling / beff -------------
__global__ void k_softmax(){
    size_t row = blockIdx.x;
    float* p = g_att + row * CC;
    int t = threadIdx.x;
    float v = p[t];
    __shared__ float red[256];
    red[t] = v; __syncthreads();
    for (int s = 128; s > 0; s >>= 1){ if (t < s) red[t] = fmaxf(red[t], red[t+s]); __syncthreads(); }
    float mx = red[0]; __syncthreads();
    float e = __expf(v - mx);
    red[t] = e; __syncthreads();
    for (int s = 128; s > 0; s >>= 1){ if (t < s) red[t] += red[t+s]; __syncthreads(); }
    float val = e / red[0];
    p[t] = val;
    int b = (int)(row >> 8);
    atomicAdd(&g_colsum[b * CC + t], val);      // fused column sum
}
// attS = att / (1e-9 + colsum[d]), split to bf16; also zeroes BN accumulators
__global__ void k_scaleAtt(){
    if (blockIdx.x == 0){ g_bns[threadIdx.x] = 0.f; g_bnq[threadIdx.x] = 0.f; }
    size_t i = ((size_t)blockIdx.x * blockDim.x + threadIdx.x) * 4;
    int b = (int)(i >> 16);
    int d = (int)(i & 255);
    float4 a  = *(const float4*)(g_att + i);
    float4 cs = *(const float4*)(g_colsum + b * CC + d);
    float v0 = a.x / (1e-9f + cs.x), v1 = a.y / (1e-9f + cs.y);
    float v2 = a.z / (1e-9f + cs.z), v3 = a.w / (1e-9f + cs.w);
    uint32_t h0,l0,h1,l1;
    split_pair(v0,v1,h0,l0); split_pair(v2,v3,h1,l1);
    *(uint2*)(g_atthi + i) = make_uint2(h0,h1);
    *(uint2*)(g_attlo + i) = make_uint2(l0,l1);
}
// beff[b][o] = bt[o] - sum_c M[b][o][c]*bv[c]
__global__ void k_beff(const float* __restrict__ bt, const float* __restrict__ bv){
    int b = blockIdx.x, o = threadIdx.x;
    const bf16* mh = g_Mhi + ((size_t)b * CC + o) * CC;
    const bf16* ml = g_Mlo + ((size_t)b * CC + o) * CC;
    float s = 0.f;
    for (int c = 0; c < CC; c++)
        s += (__bfloat162float(mh[c]) + __bfloat162float(ml[c])) * bv[c];
    g_beff[b * CC + o] = bt[o] - s;
}

// ---------------- KT7: t = x.Weff^T + beff  (K=256) + fused BN sums ---------
__global__ void __launch_bounds__(256, 2)
kt7(){
    extern __shared__ char smem[];
    int b = blockIdx.z;
    int mBase = blockIdx.x * 128;   // n
    int oBase = blockIdx.y * 64;    // o
    const bf16* Ah = g_xhi + ((size_t)b * NN + mBase) * CC;
    const bf16* Al = g_xlo + ((size_t)b * NN + mBase) * CC;
    const bf16* Bh = g_Fhi + ((size_t)b * CC + oBase) * CC;
    const bf16* Bl = g_Flo + ((size_t)b * CC + oBase) * CC;
    float acc[2][4][4] = {};
    gemm_main(smem, Ah, Al, CC, Bh, Bl, CC, 4, acc);

    int tid = threadIdx.x, lane = tid & 31, wid = tid >> 5;
    int warpM = wid & 3, warpN = wid >> 2;

    __shared__ float bn_s[64], bn_q[64];
    if (tid < 64){ bn_s[tid] = 0.f; bn_q[tid] = 0.f; }
    __syncthreads();

    int gr = lane >> 2, gc = (lane & 3) * 2;
    float sA[4][2], qA[4][2];
    #pragma unroll
    for (int nf = 0; nf < 4; nf++){
        sA[nf][0] = sA[nf][1] = qA[nf][0] = qA[nf][1] = 0.f;
        int col = warpN * 32 + nf * 8 + gc;
        int o = oBase + col;
        float b0 = g_beff[b * CC + o], b1 = g_beff[b * CC + o + 1];
        #pragma unroll
        for (int mf = 0; mf < 2; mf++){
            float* c = acc[mf][nf];
            int row0 = warpM * 32 + mf * 16 + gr;
            #pragma unroll
            for (int h = 0; h < 2; h++){
                int n = mBase + row0 + h * 8;
                float v0 = c[2*h] + b0, v1 = c[2*h+1] + b1;
                *(float2*)(g_t + ((size_t)b * NN + n) * CC + o) = make_float2(v0, v1);
                sA[nf][0] += v0;       sA[nf][1] += v1;
                qA[nf][0] += v0 * v0;  qA[nf][1] += v1 * v1;
            }
        }
    }
    #pragma unroll
    for (int nf = 0; nf < 4; nf++){
        #pragma unroll
        for (int st = 4; st < 32; st <<= 1){
            sA[nf][0] += __shfl_down_sync(0xffffffffu, sA[nf][0], st);
            sA[nf][1] += __shfl_down_sync(0xffffffffu, sA[nf][1], st);
            qA[nf][0] += __shfl_down_sync(0xffffffffu, qA[nf][0], st);
            qA[nf][1] += __shfl_down_sync(0xffffffffu, qA[nf][1], st);
        }
    }
    if (lane < 4){
        #pragma unroll
        for (int nf = 0; nf < 4; nf++){
            int colL = warpN * 32 + nf * 8 + lane * 2;
            atomicAdd(&bn_s[colL],     sA[nf][0]);
            atomicAdd(&bn_s[colL + 1], sA[nf][1]);
            atomicAdd(&bn_q[colL],     qA[nf][0]);
            atomicAdd(&bn_q[colL + 1], qA[nf][1]);
        }
    }
    __syncthreads();
    if (tid < 64){
        atomicAdd(&g_bns[oBase + tid], bn_s[tid]);
        atomicAdd(&g_bnq[oBase + tid], bn_q[tid]);
    }
}

// ---------------- BN finalize + final --------------------------------------
__global__ void k_bnfin(const float* __restrict__ gamma, const float* __restrict__ beta){
    int o = threadIdx.x;
    float inv = 1.0f / (float)(BB * NN);
    float mean = g_bns[o] * inv;
    float var  = g_bnq[o] * inv - mean * mean;
    float rstd = rsqrtf(var + 1e-5f);
    float sc = gamma[o] * rstd;
    g_scale[o] = sc;
    g_shift[o] = beta[o] - mean * sc;
}
__global__ void k_final(const float* __restrict__ x, float* __restrict__ out){
    size_t i = ((size_t)blockIdx.x * blockDim.x + threadIdx.x) * 4;
    int o = (int)(i & (CC - 1));
    float4 t4 = *(const float4*)(g_t + i);
    float4 x4 = *(const float4*)(x + i);
    float4 sc = *(const float4*)(g_scale + o);
    float4 sh = *(const float4*)(g_shift + o);
    float4 r;
    r.x = x4.x + fmaxf(fmaf(t4.x, sc.x, sh.x), 0.f);
    r.y = x4.y + fmaxf(fmaf(t4.y, sc.y, sh.y), 0.f);
    r.z = x4.z + fmaxf(fmaf(t4.z, sc.z, sh.z), 0.f);
    r.w = x4.w + fmaxf(fmaf(t4.w, sc.w, sh.w), 0.f);
    *(float4*)(out + i) = r;
}

// ---------------- launch ----------------------------------------------------
extern "C" void kernel_launch(void* const* d_in, const int* in_sizes, int n_in,
                              void* d_out, int out_size){
    (void)in_sizes; (void)n_in; (void)out_size;
    const float* x     = (const float*)d_in[1];
    const float* Wq    = (const float*)d_in[2];
    const float* Wv    = (const float*)d_in[3];
    const float* bv    = (const float*)d_in[4];
    const float* Wt    = (const float*)d_in[5];
    const float* bt    = (const float*)d_in[6];
    const float* gamma = (const float*)d_in[7];
    const float* beta  = (const float*)d_in[8];
    float* out = (float*)d_out;

    static bool init_done = false;
    if (!init_done){
        cudaFuncSetAttribute(ktG, cudaFuncAttributeMaxDynamicSharedMemorySize, SDYN);
        cudaFuncSetAttribute(ksq, cudaFuncAttributeMaxDynamicSharedMemorySize, SDYN);
        cudaFuncSetAttribute(kt7, cudaFuncAttributeMaxDynamicSharedMemorySize, SDYN);
        init_done = true;
    }

    k_cvt_x   <<<dim3(64, 4, BB), 256>>>(x);
    k_cvt_w   <<<768, 256>>>(Wq, Wv, Wt);
    ktG       <<<dim3(6, 1, 3*BB), 256, SDYN>>>();
    k_gsum    <<<1024, 256>>>();
    ksq       <<<dim3(4, 2, BB), 256, SDYN>>>(0, Wt);
    ksq       <<<dim3(4, 2, BB), 256, SDYN>>>(1, Wt);
    k_softmax <<<BB*CC, 256>>>();
    k_scaleAtt<<<1024, 256>>>();
    ksq       <<<dim3(4, 2, BB), 256, SDYN>>>(2, Wt);
    ksq       <<<dim3(4, 2, BB), 256, SDYN>>>(3, Wt);
    k_beff    <<<BB, 256>>>(bt, bv);
    kt7       <<<dim3(32, 4, BB), 256, SDYN>>>();
    k_bnfin   <<<1, 256>>>(gamma, beta);
    k_final   <<<16384, 256>>>(x, out);
}

// round 12
// speedup vs baseline: 1.5645x; 1.0300x over previous
#include <cuda_runtime.h>
#include <cuda_bf16.h>
#include <cstdint>

#define BB 16
#define NN 4096
#define CC 256

using bf16 = __nv_bfloat16;

// ---------------- scratch (device globals; no allocation allowed) ----------
__device__ __align__(16) bf16  g_xhi[(size_t)BB*NN*CC];   // x split, [B][N][C]
__device__ __align__(16) bf16  g_xlo[(size_t)BB*NN*CC];
__device__ __align__(16) bf16  g_xThi[(size_t)BB*CC*NN];  // x^T split, [B][C][N]
__device__ __align__(16) bf16  g_xTlo[(size_t)BB*CC*NN];
__device__ __align__(16) bf16  g_Whi[3*CC*CC];            // Wq, Wv, Wt split
__device__ __align__(16) bf16  g_Wlo[3*CC*CC];
__device__ __align__(16) bf16  g_WvThi[CC*CC];            // Wv^T split  [k][c]
__device__ __align__(16) bf16  g_WvTlo[CC*CC];
__device__ float g_t[(size_t)BB*NN*CC];     // pre-BN t, [B][N][C]
__device__ float g_Gp[(size_t)3*BB*CC*CC];  // split-K partials of G (3 ways)
__device__ __align__(16) bf16  g_Ghi[(size_t)BB*CC*CC];
__device__ __align__(16) bf16  g_Glo[(size_t)BB*CC*CC];
__device__ __align__(16) bf16  g_E1hi[(size_t)BB*CC*CC];
__device__ __align__(16) bf16  g_E1lo[(size_t)BB*CC*CC];
__device__ float g_att[(size_t)BB*CC*CC];
__device__ __align__(16) bf16  g_atthi[(size_t)BB*CC*CC]; // att/colsum split
__device__ __align__(16) bf16  g_attlo[(size_t)BB*CC*CC];
__device__ __align__(16) bf16  g_Mhi[(size_t)BB*CC*CC];   // M split [o][c]
__device__ __align__(16) bf16  g_Mlo[(size_t)BB*CC*CC];
__device__ __align__(16) bf16  g_Fhi[(size_t)BB*CC*CC];   // Weff = Wt - M.Wv split
__device__ __align__(16) bf16  g_Flo[(size_t)BB*CC*CC];
__device__ float g_beff[BB*CC];             // bt - M.bv
__device__ float g_colsum[BB*CC];
__device__ float g_bns[CC];                 // fused BN Σt per channel
__device__ float g_bnq[CC];                 // fused BN Σt² per channel
__device__ float g_scale[CC];
__device__ float g_shift[CC];

// Stage: Ahi(16K) Alo(16K) Bhi(8K) Blo(8K) = 48KB
#define ST_ALO 16384
#define ST_BHI 32768
#define ST_BLO 40960
#define STAGE  49152
#define SDYN2  (2*STAGE)
#define SDYN3  (3*STAGE)

// ---------------- helpers ---------------------------------------------------
__device__ __forceinline__ uint32_t smem_u32(const void* p){
    uint32_t a;
    asm("{ .reg .u64 t; cvta.to.shared.u64 t, %1; cvt.u32.u64 %0, t; }" : "=r"(a) : "l"(p));
    return a;
}
__device__ __forceinline__ uint32_t sw128(uint32_t o){ return o ^ ((o >> 3) & 0x70); }

__device__ __forceinline__ void ldm4(uint32_t* r, uint32_t addr){
    asm volatile("ldmatrix.sync.aligned.m8n8.x4.shared.b16 {%0,%1,%2,%3}, [%4];"
        : "=r"(r[0]), "=r"(r[1]), "=r"(r[2]), "=r"(r[3]) : "r"(addr));
}
__device__ __forceinline__ void mma_bf16(float* c, const uint32_t* a, const uint32_t* b){
    asm volatile("mma.sync.aligned.m16n8k16.row.col.f32.bf16.bf16.f32 "
        "{%0,%1,%2,%3}, {%4,%5,%6,%7}, {%8,%9}, {%0,%1,%2,%3};"
        : "+f"(c[0]), "+f"(c[1]), "+f"(c[2]), "+f"(c[3])
        : "r"(a[0]), "r"(a[1]), "r"(a[2]), "r"(a[3]), "r"(b[0]), "r"(b[1]));
}
__device__ __forceinline__ void cpa16(uint32_t dst, const void* src){
    asm volatile("cp.async.cg.shared.global [%0], [%1], 16;" :: "r"(dst), "l"(src));
}
__device__ __forceinline__ void split_store(bf16* hi, bf16* lo, size_t i, float v){
    bf16 h = __float2bfloat16(v);
    hi[i] = h;
    lo[i] = __float2bfloat16(v - __bfloat162float(h));
}
__device__ __forceinline__ void split_pair(float v0, float v1, uint32_t& hi, uint32_t& lo){
    bf16 h0 = __float2bfloat16(v0), h1 = __float2bfloat16(v1);
    float r0 = v0 - __bfloat162float(h0), r1 = v1 - __bfloat162float(h1);
    __nv_bfloat162 ph; ph.x = h0; ph.y = h1;
    __nv_bfloat162 pl = __floats2bfloat162_rn(r0, r1);
    hi = *(uint32_t*)&ph;
    lo = *(uint32_t*)&pl;
}

// ---------------------------------------------------------------------------
// Split-bf16 128(M)x64(N) GEMM building blocks; NS-stage cp.async pipeline.
// acc += Ahi*Bhi + Ahi*Blo + Alo*Bhi. 256 thr, warps 4(M) x 2(N), warp 32x32.
// ---------------------------------------------------------------------------
__device__ __forceinline__ void ld_chunk(char* smem, int stage, int tid,
        const bf16* __restrict__ Ahi, const bf16* __restrict__ Alo,
        const bf16* __restrict__ Bhi, const bf16* __restrict__ Blo,
        int ldA, int ldB, int c0){
    uint32_t sbase = smem_u32(smem) + stage * STAGE;
    #pragma unroll
    for (int i = 0; i < 4; i++){           // A: 128 rows x 8 segs
        int g = tid + i * 256;
        int row = g >> 3, cg = g & 7;
        uint32_t so = sw128((uint32_t)(row * 128 + cg * 16));
        size_t ga = (size_t)row * ldA + c0 + cg * 8;
        cpa16(sbase + so,          Ahi + ga);
        cpa16(sbase + ST_ALO + so, Alo + ga);
    }
    #pragma unroll
    for (int i = 0; i < 2; i++){           // B: 64 rows x 8 segs
        int g = tid + i * 256;
        int row = g >> 3, cg = g & 7;
        uint32_t so = sw128((uint32_t)(row * 128 + cg * 16));
        size_t gb = (size_t)row * ldB + c0 + cg * 8;
        cpa16(sbase + ST_BHI + so, Bhi + gb);
        cpa16(sbase + ST_BLO + so, Blo + gb);
    }
    asm volatile("cp.async.commit_group;" ::: "memory");
}

__device__ __forceinline__ void compute_chunk(uint32_t sb, int lane,
        int warpM, int warpN, float acc[2][4][4]){
    #pragma unroll
    for (int ks = 0; ks < 4; ks++){
        uint32_t ahi[2][4], alo[2][4];
        #pragma unroll
        for (int mf = 0; mf < 2; mf++){
            int row = warpM * 32 + mf * 16 + (lane & 15);
            uint32_t off = sw128((uint32_t)(row * 128 + ks * 32 + (lane >> 4) * 16));
            ldm4(ahi[mf], sb + off);
            ldm4(alo[mf], sb + ST_ALO + off);
        }
        #pragma unroll
        for (int ng = 0; ng < 2; ng++){
            int rowb = warpN * 32 + ng * 16 + (lane & 15);
            uint32_t off = sw128((uint32_t)(rowb * 128 + ks * 32 + (lane >> 4) * 16));
            uint32_t bh[4], bl[4];
            ldm4(bh, sb + ST_BHI + off);
            ldm4(bl, sb + ST_BLO + off);
            uint32_t bh0[2] = {bh[0], bh[2]}, bh1[2] = {bh[1], bh[3]};
            uint32_t bl0[2] = {bl[0], bl[2]}, bl1[2] = {bl[1], bl[3]};
            #pragma unroll
            for (int mf = 0; mf < 2; mf++){
                mma_bf16(acc[mf][ng*2],     ahi[mf], bh0);
                mma_bf16(acc[mf][ng*2],     ahi[mf], bl0);
                mma_bf16(acc[mf][ng*2],     alo[mf], bh0);
                mma_bf16(acc[mf][ng*2 + 1], ahi[mf], bh1);
                mma_bf16(acc[mf][ng*2 + 1], ahi[mf], bl1);
                mma_bf16(acc[mf][ng*2 + 1], alo[mf], bh1);
            }
        }
    }
}

template<int NS>
__device__ __forceinline__ void gemm_main(char* smem,
        const bf16* __restrict__ Ahi, const bf16* __restrict__ Alo, int ldA,
        const bf16* __restrict__ Bhi, const bf16* __restrict__ Blo, int ldB,
        int nChunks, float acc[2][4][4])
{
    int tid = threadIdx.x, lane = tid & 31, wid = tid >> 5;
    int warpM = wid & 3, warpN = wid >> 2;
    uint32_t sb0 = smem_u32(smem);

    int issued = 0, ldst = 0, cst = 0;
    int npre = (nChunks < NS - 1) ? nChunks : (NS - 1);
    for (int i = 0; i < npre; i++){
        ld_chunk(smem, ldst, tid, Ahi, Alo, Bhi, Blo, ldA, ldB, issued * 64);
        issued++; ldst = (ldst + 1 == NS) ? 0 : ldst + 1;
    }
    for (int cc = 0; cc < nChunks; cc++){
        if (issued < nChunks){
            ld_chunk(smem, ldst, tid, Ahi, Alo, Bhi, Blo, ldA, ldB, issued * 64);
            issued++; ldst = (ldst + 1 == NS) ? 0 : ldst + 1;
        }
        int pend = issued - cc - 1;
        if (pend >= 2)      asm volatile("cp.async.wait_group 2;" ::: "memory");
        else if (pend == 1) asm volatile("cp.async.wait_group 1;" ::: "memory");
        else                asm volatile("cp.async.wait_group 0;" ::: "memory");
        __syncthreads();
        compute_chunk(sb0 + cst * STAGE, lane, warpM, warpN, acc);
        cst = (cst + 1 == NS) ? 0 : cst + 1;
        __syncthreads();
    }
}

// ---------------- conversion: x -> split x AND split x^T --------------------
__global__ void __launch_bounds__(256) k_cvt_x(const float* __restrict__ x){
    int b = blockIdx.z, n0 = blockIdx.x * 64, c0 = blockIdx.y * 64;
    __shared__ float xs[64][65];
    int t = threadIdx.x;
    const float* xb = x + ((size_t)b * NN + n0) * CC + c0;
    #pragma unroll
    for (int p = 0; p < 4; p++){
        int row = p * 16 + (t >> 4);
        int c4  = (t & 15) * 4;
        float4 v = *(const float4*)(xb + (size_t)row * CC + c4);
        uint32_t h0, l0, h1, l1;
        split_pair(v.x, v.y, h0, l0);
        split_pair(v.z, v.w, h1, l1);
        size_t di = ((size_t)b * NN + n0 + row) * CC + c0 + c4;
        *(uint2*)(g_xhi + di) = make_uint2(h0, h1);
        *(uint2*)(g_xlo + di) = make_uint2(l0, l1);
        xs[row][c4 + 0] = v.x; xs[row][c4 + 1] = v.y;
        xs[row][c4 + 2] = v.z; xs[row][c4 + 3] = v.w;
    }
    __syncthreads();
    #pragma unroll
    for (int p = 0; p < 4; p++){
        int cl = p * 16 + (t >> 4);
        int n4 = (t & 15) * 4;
        float v0 = xs[n4][cl], v1 = xs[n4+1][cl], v2 = xs[n4+2][cl], v3 = xs[n4+3][cl];
        uint32_t h0, l0, h1, l1;
        split_pair(v0, v1, h0, l0);
        split_pair(v2, v3, h1, l1);
        size_t di = ((size_t)b * CC + c0 + cl) * NN + n0 + n4;
        *(uint2*)(g_xThi + di) = make_uint2(h0, h1);
        *(uint2*)(g_xTlo + di) = make_uint2(l0, l1);
    }
}
__global__ void k_cvt_w(const float* __restrict__ Wq, const float* __restrict__ Wv,
                        const float* __restrict__ Wt){
    // side duty: zero colsum accumulators (softmax atomics add into them later)
    if (blockIdx.x < 16) g_colsum[blockIdx.x * 256 + threadIdx.x] = 0.f;
    int idx = blockIdx.x * blockDim.x + threadIdx.x;
    int which = idx >> 16, rem = idx & 65535;
    const float* s = (which == 0) ? Wq : (which == 1) ? Wv : Wt;
    float v = s[rem];
    split_store(g_Whi, g_Wlo, idx, v);
    if (which == 1){
        int o = rem >> 8, c = rem & 255;          // Wv[o][c] -> WvT[c][o]
        split_store(g_WvThi, g_WvTlo, (size_t)c * CC + o, v);
    }
}

// ---------------- KTG: G = x^T x (split-K x3, symmetric: 6 of 8 tiles) ------
// 3-stage pipeline, 1 CTA/SM (deep prefetch pays off at K=21-22 chunks)
__constant__ int c_tileC[6] = {0, 0, 0, 0, 128, 128};
__constant__ int c_tileD[6] = {0, 64, 128, 192, 128, 192};
__constant__ int c_ks0[3] = {0, 22, 43};    // chunk start (64-wide chunks)
__constant__ int c_ksn[3] = {22, 21, 21};   // chunk count
__global__ void __launch_bounds__(256, 1)
ktG(){
    extern __shared__ char smem[];
    int b = blockIdx.z / 3, ks = blockIdx.z % 3;
    int cBase = c_tileC[blockIdx.x], dBase = c_tileD[blockIdx.x];
    size_t kOff = (size_t)c_ks0[ks] * 64;
    int nch = c_ksn[ks];
    const bf16* Ah = g_xThi + ((size_t)b * CC + cBase) * NN + kOff;
    const bf16* Al = g_xTlo + ((size_t)b * CC + cBase) * NN + kOff;
    const bf16* Bh = g_xThi + ((size_t)b * CC + dBase) * NN + kOff;
    const bf16* Bl = g_xTlo + ((size_t)b * CC + dBase) * NN + kOff;
    float acc[2][4][4] = {};
    gemm_main<3>(smem, Ah, Al, NN, Bh, Bl, NN, nch, acc);

    int tid = threadIdx.x, lane = tid & 31, wid = tid >> 5;
    int warpM = wid & 3, warpN = wid >> 2;
    int gr = lane >> 2, gc = (lane & 3) * 2;
    float* dst = g_Gp + ((size_t)(ks * BB + b)) * CC * CC;
    #pragma unroll
    for (int mf = 0; mf < 2; mf++)
        #pragma unroll
        for (int nf = 0; nf < 4; nf++){
            float* c = acc[mf][nf];
            int row0 = warpM * 32 + mf * 16 + gr;
            int col  = warpN * 32 + nf * 8 + gc;
            #pragma unroll
            for (int h = 0; h < 2; h++)
                *(float2*)(dst + (size_t)(cBase + row0 + h*8) * CC + dBase + col)
                    = make_float2(c[2*h], c[2*h+1]);
        }
}
// sum split-K partials; mirror the uncomputed lower-left quadrant (r>=128,c<128)
__global__ void k_gsum(){
    size_t i = ((size_t)blockIdx.x * blockDim.x + threadIdx.x) * 4;
    const size_t S = (size_t)BB * CC * CC;
    int b  = (int)(i >> 16);
    int rc = (int)(i & 65535);
    int r = rc >> 8, c0 = rc & 255;
    float v[4];
    if (r >= 128 && c0 < 128){
        #pragma unroll
        for (int j = 0; j < 4; j++){
            size_t src = (size_t)b * CC * CC + (size_t)(c0 + j) * CC + r;  // transposed
            v[j] = g_Gp[src] + g_Gp[S + src] + g_Gp[2*S + src];
        }
    } else {
        float4 a = *(const float4*)(g_Gp + i);
        float4 bb = *(const float4*)(g_Gp + S + i);
        float4 cc = *(const float4*)(g_Gp + 2*S + i);
        v[0] = a.x+bb.x+cc.x; v[1] = a.y+bb.y+cc.y;
        v[2] = a.z+bb.z+cc.z; v[3] = a.w+bb.w+cc.w;
    }
    uint32_t h0,l0,h1,l1;
    split_pair(v[0],v[1],h0,l0); split_pair(v[2],v[3],h1,l1);
    *(uint2*)(g_Ghi + i) = make_uint2(h0,h1);
    *(uint2*)(g_Glo + i) = make_uint2(l0,l1);
}

// ---------------- small square GEMMs (K=256) --------------------------------
// mode 0: E1 = Wq.G            -> split E1
// mode 1: E  = E1.Wq^T         -> fp32 g_att
// mode 2: M  = Wt.attS         -> split M
// mode 3: Weff = Wt - M.Wv     -> split F; nBase==0 CTAs also compute beff
__global__ void __launch_bounds__(256, 2)
ksq(int mode, const float* __restrict__ Wt,
    const float* __restrict__ bt, const float* __restrict__ bv){
    extern __shared__ char smem[];
    int b = blockIdx.z;
    int mBase = blockIdx.y * 128, nBase = blockIdx.x * 64;
    size_t boff = (size_t)b * CC * CC;
    const bf16 *Ah, *Al, *Bh, *Bl;
    if (mode == 0){
        Ah = g_Whi + mBase * CC;        Al = g_Wlo + mBase * CC;
        Bh = g_Ghi + boff + nBase * CC; Bl = g_Glo + boff + nBase * CC;
    } else if (mode == 1){
        Ah = g_E1hi + boff + mBase * CC; Al = g_E1lo + boff + mBase * CC;
        Bh = g_Whi + nBase * CC;         Bl = g_Wlo + nBase * CC;
    } else if (mode == 2){
        Ah = g_Whi + 2*CC*CC + mBase * CC; Al = g_Wlo + 2*CC*CC + mBase * CC;
        Bh = g_atthi + boff + nBase * CC;  Bl = g_attlo + boff + nBase * CC;
    } else {
        Ah = g_Mhi + boff + mBase * CC;  Al = g_Mlo + boff + mBase * CC;
        Bh = g_WvThi + nBase * CC;       Bl = g_WvTlo + nBase * CC;
    }
    float acc[2][4][4] = {};
    gemm_main<2>(smem, Ah, Al, CC, Bh, Bl, CC, 4, acc);

    int tid = threadIdx.x, lane = tid & 31, wid = tid >> 5;
    int warpM = wid & 3, warpN = wid >> 2;
    int gr = lane >> 2, gc = (lane & 3) * 2;
    #pragma unroll
    for (int mf = 0; mf < 2; mf++)
        #pragma unroll
        for (int nf = 0; nf < 4; nf++){
            float* c = acc[mf][nf];
            int row0 = warpM * 32 + mf * 16 + gr;
            int col  = warpN * 32 + nf * 8 + gc;
            #pragma unroll
            for (int h = 0; h < 2; h++){
                int rr = mBase + row0 + h*8, kk = nBase + col;
                size_t di = boff + (size_t)rr * CC + kk;
                if (mode == 1){
                    *(float2*)(g_att + di) = make_float2(c[2*h], c[2*h+1]);
                } else if (mode == 0){
                    uint32_t hi, lo;
                    split_pair(c[2*h], c[2*h+1], hi, lo);
                    *(uint32_t*)(g_E1hi + di) = hi; *(uint32_t*)(g_E1lo + di) = lo;
                } else if (mode == 2){
                    uint32_t hi, lo;
                    split_pair(c[2*h], c[2*h+1], hi, lo);
                    *(uint32_t*)(g_Mhi + di) = hi; *(uint32_t*)(g_Mlo + di) = lo;
                } else {
                    float w0 = Wt[(size_t)rr * CC + kk];
                    float w1 = Wt[(size_t)rr * CC + kk + 1];
                    uint32_t hi, lo;
                    split_pair(w0 - c[2*h], w1 - c[2*h+1], hi, lo);
                    *(uint32_t*)(g_Fhi + di) = hi; *(uint32_t*)(g_Flo + di) = lo;
                }
            }
        }
    // fused beff: one CTA column per (b, mBase) computes beff rows
    if (mode == 3 && blockIdx.x == 0 && tid < 128){
        int o = mBase + tid;
        const bf16* mh = g_Mhi + boff + (size_t)o * CC;
        const bf16* ml = g_Mlo + boff + (size_t)o * CC;
        float s = 0.f;
        for (int c = 0; c < CC; c++)
            s += (__bfloat162float(mh[c]) + __bfloat162float(ml[c])) * bv[c];
        g_beff[b * CC + o] = bt[o] - s;
    }
}

// ---------------- softmax (+ fused colsum) / att scaling --------------------
__global__ void k_softmax(){
    size_t row = blockIdx.x;
    float* p = g_att + row * CC;
    int t = threadIdx.x, lane = t & 31, w = t >> 5;
    float v = p[t];
    __shared__ float wred[8];
    float m = v;
    #pragma unroll
    for (int o = 16; o > 0; o >>= 1) m = fmaxf(m, __shfl_xor_sync(0xffffffffu, m, o));
    if (lane == 0) wred[w] = m;
    __syncthreads();
    float mx = wred[0];
    #pragma unroll
    for (int i = 1; i < 8; i++) mx = fmaxf(mx, wred[i]);
    float e = __expf(v - mx);
    float s = e;
    #pragma unroll
    for (int o = 16; o > 0; o >>= 1) s += __shfl_xor_sync(0xffffffffu, s, o);
    __syncthreads();
    if (lane == 0) wred[w] = s;
    __syncthreads();
    float tot = 0.f;
    #pragma unroll
    for (int i = 0; i < 8; i++) tot += wred[i];
    float val = e / tot;
    p[t] = val;
    int b = (int)(row >> 8);
    atomicAdd(&g_colsum[b * CC + t], val);      // fused column sum
}
// attS = att / (1e-9 + colsum[d]), split to bf16; also zeroes BN accumulators
__global__ void k_scaleAtt(){
    if (blockIdx.x == 0){ g_bns[threadIdx.x] = 0.f; g_bnq[threadIdx.x] = 0.f; }
    size_t i = ((size_t)blockIdx.x * blockDim.x + threadIdx.x) * 4;
    int b = (int)(i >> 16);
    int d = (int)(i & 255);
    float4 a  = *(const float4*)(g_att + i);
    float4 cs = *(const float4*)(g_colsum + b * CC + d);
    float v0 = a.x / (1e-9f + cs.x), v1 = a.y / (1e-9f + cs.y);
    float v2 = a.z / (1e-9f + cs.z), v3 = a.w / (1e-9f + cs.w);
    uint32_t h0,l0,h1,l1;
    split_pair(v0,v1,h0,l0); split_pair(v2,v3,h1,l1);
    *(uint2*)(g_atthi + i) = make_uint2(h0,h1);
    *(uint2*)(g_attlo + i) = make_uint2(l0,l1);
}

// ---------------- KT7: t = x.Weff^T + beff  (K=256) + fused BN sums ---------
__global__ void __launch_bounds__(256, 2)
kt7(){
    extern __shared__ char smem[];
    int b = blockIdx.z;
    int mBase = blockIdx.x * 128;   // n
    int oBase = blockIdx.y * 64;    // o
    const bf16* Ah = g_xhi + ((size_t)b * NN + mBase) * CC;
    const bf16* Al = g_xlo + ((size_t)b * NN + mBase) * CC;
    const bf16* Bh = g_Fhi + ((size_t)b * CC + oBase) * CC;
    const bf16* Bl = g_Flo + ((size_t)b * CC + oBase) * CC;
    float acc[2][4][4] = {};
    gemm_main<2>(smem, Ah, Al, CC, Bh, Bl, CC, 4, acc);

    int tid = threadIdx.x, lane = tid & 31, wid = tid >> 5;
    int warpM = wid & 3, warpN = wid >> 2;

    __shared__ float bn_s[64], bn_q[64];
    if (tid < 64){ bn_s[tid] = 0.f; bn_q[tid] = 0.f; }
    __syncthreads();

    int gr = lane >> 2, gc = (lane & 3) * 2;
    float sA[4][2], qA[4][2];
    #pragma unroll
    for (int nf = 0; nf < 4; nf++){
        sA[nf][0] = sA[nf][1] = qA[nf][0] = qA[nf][1] = 0.f;
        int col = warpN * 32 + nf * 8 + gc;
        int o = oBase + col;
        float b0f = g_beff[b * CC + o], b1f = g_beff[b * CC + o + 1];
        #pragma unroll
        for (int mf = 0; mf < 2; mf++){
            float* c = acc[mf][nf];
            int row0 = warpM * 32 + mf * 16 + gr;
            #pragma unroll
            for (int h = 0; h < 2; h++){
                int n = mBase + row0 + h * 8;
                float v0 = c[2*h] + b0f, v1 = c[2*h+1] + b1f;
                *(float2*)(g_t + ((size_t)b * NN + n) * CC + o) = make_float2(v0, v1);
                sA[nf][0] += v0;       sA[nf][1] += v1;
                qA[nf][0] += v0 * v0;  qA[nf][1] += v1 * v1;
            }
        }
    }
    #pragma unroll
    for (int nf = 0; nf < 4; nf++){
        #pragma unroll
        for (int st = 4; st < 32; st <<= 1){
            sA[nf][0] += __shfl_down_sync(0xffffffffu, sA[nf][0], st);
            sA[nf][1] += __shfl_down_sync(0xffffffffu, sA[nf][1], st);
            qA[nf][0] += __shfl_down_sync(0xffffffffu, qA[nf][0], st);
            qA[nf][1] += __shfl_down_sync(0xffffffffu, qA[nf][1], st);
        }
    }
    if (lane < 4){
        #pragma unroll
        for (int nf = 0; nf < 4; nf++){
            int colL = warpN * 32 + nf * 8 + lane * 2;
            atomicAdd(&bn_s[colL],     sA[nf][0]);
            atomicAdd(&bn_s[colL + 1], sA[nf][1]);
            atomicAdd(&bn_q[colL],     qA[nf][0]);
            atomicAdd(&bn_q[colL + 1], qA[nf][1]);
        }
    }
    __syncthreads();
    if (tid < 64){
        atomicAdd(&g_bns[oBase + tid], bn_s[tid]);
        atomicAdd(&g_bnq[oBase + tid], bn_q[tid]);
    }
}

// ---------------- BN finalize + final --------------------------------------
__global__ void k_bnfin(const float* __restrict__ gamma, const float* __restrict__ beta){
    int o = threadIdx.x;
    float inv = 1.0f / (float)(BB * NN);
    float mean = g_bns[o] * inv;
    float var  = g_bnq[o] * inv - mean * mean;
    float rstd = rsqrtf(var + 1e-5f);
    float sc = gamma[o] * rstd;
    g_scale[o] = sc;
    g_shift[o] = beta[o] - mean * sc;
}
__global__ void k_final(const float* __restrict__ x, float* __restrict__ out){
    size_t i = ((size_t)blockIdx.x * blockDim.x + threadIdx.x) * 4;
    int o = (int)(i & (CC - 1));
    float4 t4 = *(const float4*)(g_t + i);
    float4 x4 = *(const float4*)(x + i);
    float4 sc = *(const float4*)(g_scale + o);
    float4 sh = *(const float4*)(g_shift + o);
    float4 r;
    r.x = x4.x + fmaxf(fmaf(t4.x, sc.x, sh.x), 0.f);
    r.y = x4.y + fmaxf(fmaf(t4.y, sc.y, sh.y), 0.f);
    r.z = x4.z + fmaxf(fmaf(t4.z, sc.z, sh.z), 0.f);
    r.w = x4.w + fmaxf(fmaf(t4.w, sc.w, sh.w), 0.f);
    *(float4*)(out + i) = r;
}

// ---------------- launch ----------------------------------------------------
extern "C" void kernel_launch(void* const* d_in, const int* in_sizes, int n_in,
                              void* d_out, int out_size){
    (void)in_sizes; (void)n_in; (void)out_size;
    const float* x     = (const float*)d_in[1];
    const float* Wq    = (const float*)d_in[2];
    const float* Wv    = (const float*)d_in[3];
    const float* bv    = (const float*)d_in[4];
    const float* Wt    = (const float*)d_in[5];
    const float* bt    = (const float*)d_in[6];
    const float* gamma = (const float*)d_in[7];
    const float* beta  = (const float*)d_in[8];
    float* out = (float*)d_out;

    static bool init_done = false;
    if (!init_done){
        cudaFuncSetAttribute(ktG, cudaFuncAttributeMaxDynamicSharedMemorySize, SDYN3);
        cudaFuncSetAttribute(ksq, cudaFuncAttributeMaxDynamicSharedMemorySize, SDYN2);
        cudaFuncSetAttribute(kt7, cudaFuncAttributeMaxDynamicSharedMemorySize, SDYN2);
        init_done = true;
    }

    k_cvt_x   <<<dim3(64, 4, BB), 256>>>(x);
    k_cvt_w   <<<768, 256>>>(Wq, Wv, Wt);
    ktG       <<<dim3(6, 1, 3*BB), 256, SDYN3>>>();
    k_gsum    <<<1024, 256>>>();
    ksq       <<<dim3(4, 2, BB), 256, SDYN2>>>(0, Wt, bt, bv);
    ksq       <<<dim3(4, 2, BB), 256, SDYN2>>>(1, Wt, bt, bv);
    k_softmax <<<BB*CC, 256>>>();
    k_scaleAtt<<<1024, 256>>>();
    ksq       <<<dim3(4, 2, BB), 256, SDYN2>>>(2, Wt, bt, bv);
    ksq       <<<dim3(4, 2, BB), 256, SDYN2>>>(3, Wt, bt, bv);
    kt7       <<<dim3(32, 4, BB), 256, SDYN2>>>();
    k_bnfin   <<<1, 256>>>(gamma, beta);
    k_final   <<<16384, 256>>>(x, out);
}